// round 2
// baseline (speedup 1.0000x reference)
#include <cuda_runtime.h>
#include <math.h>

// ---------------- problem dims (fixed by setup_inputs) ----------------
#define NA    100000      // atoms
#define MM    12          // neighbors per atom
#define ORIG  92          // input atom feature dim
#define NBRF  41          // neighbor (bond) feature dim
#define FF    64          // hidden feature dim
#define HH    128         // fc hidden
#define BB    2000        // crystals
#define NCONV 3
#define NM    (NA*MM)     // 1.2M edge rows
#define TWOF  (2*FF)      // 128
#define WF_ROWS (2*FF + NBRF)         // 169
#define WF_STRIDE (WF_ROWS * TWOF)    // 169*128 per layer

// ---------------- scratch (device globals; no allocation) -------------
__device__ float  g_h[NA * FF];                 // 25.6 MB
__device__ float  g_A[NA * TWOF];               // 51.2 MB  h @ Wf_self
__device__ float  g_P[NA * TWOF];               // 51.2 MB  h @ Wf_nbr
__device__ float  g_G[1200000 * 128];           // 614 MB   gated pre-BN
__device__ float  g_summed[NA * FF];            // 25.6 MB
__device__ double g_stat1[2 * TWOF];            // sum / sumsq (128 cols)
__device__ double g_stat2[2 * FF];              // sum / sumsq (64 cols)
__device__ float  g_bn1[2 * TWOF];              // scale(128), shift(128)
__device__ float  g_bn2[2 * FF];                // scale(64), shift(64)
__device__ float  g_pool[BB * FF];
__device__ float  g_cnt[BB];

// ---------------- helpers ----------------
__device__ __forceinline__ float softplusf_(float x) {
    // stable: max(x,0) + log1p(exp(-|x|))
    return fmaxf(x, 0.f) + log1pf(__expf(-fabsf(x)));
}
__device__ __forceinline__ float sigmoidf_(float x) {
    return 1.f / (1.f + __expf(-x));
}

// ---------------- kernels ----------------

// h = atom_fea @ W_emb + b_emb    [NA,92]@[92,64]
__global__ void k_embed(const float* __restrict__ atom,
                        const float* __restrict__ W,
                        const float* __restrict__ b) {
    __shared__ float sW[ORIG * FF];
    __shared__ float sb[FF];
    __shared__ float sa[ORIG];
    int tid = threadIdx.x;            // 64 threads
    for (int i = tid; i < ORIG * FF; i += 64) sW[i] = W[i];
    if (tid < FF) sb[tid] = b[tid];
    __syncthreads();
    for (int r = 0; r < 64; r++) {
        int row = blockIdx.x * 64 + r;
        if (row >= NA) break;                    // uniform per block
        __syncthreads();
        for (int i = tid; i < ORIG; i += 64) sa[i] = atom[row * ORIG + i];
        __syncthreads();
        float acc = sb[tid];
        #pragma unroll 4
        for (int k = 0; k < ORIG; k++) acc = fmaf(sa[k], sW[k * FF + tid], acc);
        g_h[row * FF + tid] = acc;
    }
}

// A[n,j] = sum_k h[n,k] * Wf[k,j];  P[n,j] = sum_k h[n,k] * Wf[64+k,j]
// block: 128 threads (one column each), 4 rows per block
__global__ void __launch_bounds__(128) k_AP(const float* __restrict__ Wf) {
    __shared__ float sh[4][FF];
    int j = threadIdx.x;              // 0..127
    int n0 = blockIdx.x * 4;
    for (int i = j; i < 4 * FF; i += 128) {
        int r = i >> 6, k = i & 63;
        sh[r][k] = g_h[(n0 + r) * FF + k];   // NA divisible by 4
    }
    __syncthreads();
    float a0 = 0, a1 = 0, a2 = 0, a3 = 0;
    float p0 = 0, p1 = 0, p2 = 0, p3 = 0;
    #pragma unroll
    for (int k = 0; k < FF; k++) {
        float wa = __ldg(&Wf[k * TWOF + j]);
        float wb = __ldg(&Wf[(FF + k) * TWOF + j]);
        a0 = fmaf(sh[0][k], wa, a0); p0 = fmaf(sh[0][k], wb, p0);
        a1 = fmaf(sh[1][k], wa, a1); p1 = fmaf(sh[1][k], wb, p1);
        a2 = fmaf(sh[2][k], wa, a2); p2 = fmaf(sh[2][k], wb, p2);
        a3 = fmaf(sh[3][k], wa, a3); p3 = fmaf(sh[3][k], wb, p3);
    }
    g_A[(n0 + 0) * TWOF + j] = a0;  g_P[(n0 + 0) * TWOF + j] = p0;
    g_A[(n0 + 1) * TWOF + j] = a1;  g_P[(n0 + 1) * TWOF + j] = p1;
    g_A[(n0 + 2) * TWOF + j] = a2;  g_P[(n0 + 2) * TWOF + j] = p2;
    g_A[(n0 + 3) * TWOF + j] = a3;  g_P[(n0 + 3) * TWOF + j] = p3;
}

__global__ void k_zero_stats() {
    int i = threadIdx.x;
    if (i < 2 * TWOF) g_stat1[i] = 0.0;
    if (i < 2 * FF)   g_stat2[i] = 0.0;
}

// G[n*M+m, j] = A[n,j] + P[idx[n,m],j] + nbr_fea[n,m,:] @ Wf_nf[:,j] + bf[j]
// + column sum/sumsq stats. Block: 128 threads (one col each), 8 atoms/block.
#define G_NPB 8
__global__ void __launch_bounds__(128) k_G(const float* __restrict__ nbr_fea,
                    const int*   __restrict__ idx,
                    const float* __restrict__ Wf,
                    const float* __restrict__ bf) {
    int j = threadIdx.x;                      // 0..127
    __shared__ float snf[MM * NBRF];          // 492 floats
    __shared__ int   sidx[MM];
    float wc[NBRF];
    #pragma unroll
    for (int k = 0; k < NBRF; k++) wc[k] = __ldg(&Wf[(TWOF + k) * TWOF + j]);
    float bfj = __ldg(&bf[j]);
    float s = 0.f, s2 = 0.f;
    int nStart = blockIdx.x * G_NPB;
    for (int n = nStart; n < nStart + G_NPB; n++) {   // NA divisible by 8
        __syncthreads();
        for (int i = j; i < MM * NBRF; i += 128)
            snf[i] = nbr_fea[(size_t)n * (MM * NBRF) + i];
        if (j < MM) sidx[j] = idx[n * MM + j];
        __syncthreads();
        float a = g_A[n * TWOF + j];
        for (int m = 0; m < MM; m++) {
            int nb = sidx[m];
            float acc = a + __ldg(&g_P[nb * TWOF + j]) + bfj;
            const float* nf = snf + m * NBRF;
            #pragma unroll
            for (int k = 0; k < NBRF; k++) acc = fmaf(nf[k], wc[k], acc);
            g_G[((size_t)n * MM + m) * TWOF + j] = acc;
            s += acc;
            s2 = fmaf(acc, acc, s2);
        }
    }
    atomicAdd(&g_stat1[j], (double)s);
    atomicAdd(&g_stat1[TWOF + j], (double)s2);
}

// Compute BN affine params from accumulated stats.
// which==0 -> bn1 (128 cols over N*M rows), which==1 -> bn2 (64 cols over N rows)
__global__ void k_bnparam(int which,
                          const float* __restrict__ gamma,
                          const float* __restrict__ beta) {
    int j = threadIdx.x;
    if (which == 0) {
        if (j >= TWOF) return;
        double inv = 1.0 / (double)NM;
        double mu = g_stat1[j] * inv;
        double var = g_stat1[TWOF + j] * inv - mu * mu;
        float sc = gamma[j] * rsqrtf((float)var + 1e-5f);
        g_bn1[j] = sc;
        g_bn1[TWOF + j] = beta[j] - (float)mu * sc;
    } else {
        if (j >= FF) return;
        double inv = 1.0 / (double)NA;
        double mu = g_stat2[j] * inv;
        double var = g_stat2[FF + j] * inv - mu * mu;
        float sc = gamma[j] * rsqrtf((float)var + 1e-5f);
        g_bn2[j] = sc;
        g_bn2[FF + j] = beta[j] - (float)mu * sc;
    }
}

// summed[n,j] = sum_m sigmoid(bn(Gf)) * softplus(bn(Gc)); + stats over n.
// 256 threads = 4 groups of 64 cols; each group walks 16 atoms.
__global__ void __launch_bounds__(256) k_S() {
    int tid = threadIdx.x;
    int j = tid & 63;
    int grp = tid >> 6;                       // 0..3
    float scf = g_bn1[j],        shf = g_bn1[TWOF + j];
    float scc = g_bn1[FF + j],   shc = g_bn1[TWOF + FF + j];
    float s = 0.f, s2 = 0.f;
    int nBase = blockIdx.x * 64 + grp * 16;
    for (int t = 0; t < 16; t++) {
        int n = nBase + t;
        if (n >= NA) break;                   // uniform within 2-warp group
        float acc = 0.f;
        size_t r0 = (size_t)n * MM;
        for (int m = 0; m < MM; m++) {
            const float* gr = g_G + (r0 + m) * TWOF;
            float xf = fmaf(scf, __ldg(&gr[j]), shf);
            float xc = fmaf(scc, __ldg(&gr[FF + j]), shc);
            acc = fmaf(sigmoidf_(xf), softplusf_(xc), acc);
        }
        g_summed[n * FF + j] = acc;
        s += acc;
        s2 = fmaf(acc, acc, s2);
    }
    atomicAdd(&g_stat2[j], (double)s);
    atomicAdd(&g_stat2[FF + j], (double)s2);
}

// h = softplus(h + bn2(summed))
__global__ void k_H() {
    int i = blockIdx.x * blockDim.x + threadIdx.x;
    if (i >= NA * FF) return;
    int j = i & 63;
    float x = fmaf(g_bn2[j], g_summed[i], g_bn2[FF + j]);
    g_h[i] = softplusf_(g_h[i] + x);
}

__global__ void k_zero_pool() {
    int i = blockIdx.x * 256 + threadIdx.x;
    if (i < BB * FF) g_pool[i] = 0.f;
    if (i < BB) g_cnt[i] = 0.f;
}

__global__ void k_pool(const int* __restrict__ cid) {
    int n = blockIdx.x;
    int c = cid[n];
    atomicAdd(&g_pool[c * FF + threadIdx.x], g_h[n * FF + threadIdx.x]);
    if (threadIdx.x == 0) atomicAdd(&g_cnt[c], 1.f);
}

// crys = pool/cnt; out[b] = softplus(crys@W_fc + b_fc) @ W_out + b_out
__global__ void k_head(const float* __restrict__ Wfc,
                       const float* __restrict__ bfc,
                       const float* __restrict__ Wout,
                       const float* __restrict__ bout,
                       float* __restrict__ out) {
    int b = blockIdx.x;
    int t = threadIdx.x;                      // 128
    __shared__ float sc[FF];
    __shared__ float red[HH];
    float inv = 1.f / fmaxf(g_cnt[b], 1.f);
    if (t < FF) sc[t] = g_pool[b * FF + t] * inv;
    __syncthreads();
    float acc = bfc[t];
    #pragma unroll
    for (int k = 0; k < FF; k++) acc = fmaf(sc[k], __ldg(&Wfc[k * HH + t]), acc);
    red[t] = softplusf_(acc) * __ldg(&Wout[t]);
    __syncthreads();
    for (int off = 64; off > 0; off >>= 1) {
        if (t < off) red[t] += red[t + off];
        __syncthreads();
    }
    if (t == 0) out[b] = red[0] + bout[0];
}

// ---------------- launch ----------------
extern "C" void kernel_launch(void* const* d_in, const int* in_sizes, int n_in,
                              void* d_out, int out_size) {
    const float* atom_fea = (const float*)d_in[0];
    const float* nbr_fea  = (const float*)d_in[1];
    const int*   nbr_idx  = (const int*)d_in[2];
    const int*   cid      = (const int*)d_in[3];
    // num_crystals may or may not appear as a scalar input
    int o = (n_in >= 17 && in_sizes[4] == 1) ? 1 : 0;
    const float* W_emb = (const float*)d_in[4 + o];
    const float* b_emb = (const float*)d_in[5 + o];
    const float* Wf    = (const float*)d_in[6 + o];
    const float* bf    = (const float*)d_in[7 + o];
    const float* g1    = (const float*)d_in[8 + o];
    const float* b1    = (const float*)d_in[9 + o];
    const float* g2    = (const float*)d_in[10 + o];
    const float* b2    = (const float*)d_in[11 + o];
    const float* W_fc  = (const float*)d_in[12 + o];
    const float* b_fc  = (const float*)d_in[13 + o];
    const float* W_out = (const float*)d_in[14 + o];
    const float* b_out = (const float*)d_in[15 + o];
    float* out = (float*)d_out;

    k_embed<<<(NA + 63) / 64, 64>>>(atom_fea, W_emb, b_emb);

    for (int l = 0; l < NCONV; l++) {
        const float* Wfl = Wf + l * WF_STRIDE;
        const float* bfl = bf + l * TWOF;
        const float* g1l = g1 + l * TWOF;
        const float* b1l = b1 + l * TWOF;
        const float* g2l = g2 + l * FF;
        const float* b2l = b2 + l * FF;

        k_zero_stats<<<1, 256>>>();
        k_AP<<<NA / 4, 128>>>(Wfl);
        k_G<<<NA / G_NPB, 128>>>(nbr_fea, nbr_idx, Wfl, bfl);
        k_bnparam<<<1, 128>>>(0, g1l, b1l);
        k_S<<<(NA + 63) / 64, 256>>>();
        k_bnparam<<<1, 64>>>(1, g2l, b2l);
        k_H<<<(NA * FF) / 256, 256>>>();
    }

    k_zero_pool<<<(BB * FF + 255) / 256, 256>>>();
    k_pool<<<NA, FF>>>(cid);
    k_head<<<BB, HH>>>(W_fc, b_fc, W_out, b_out, out);
}

// round 3
// speedup vs baseline: 1.0984x; 1.0984x over previous
#include <cuda_runtime.h>
#include <math.h>

// ---------------- problem dims (fixed by setup_inputs) ----------------
#define NA    100000      // atoms
#define MM    12          // neighbors per atom
#define ORIG  92          // input atom feature dim
#define NBRF  41          // neighbor (bond) feature dim
#define FF    64          // hidden feature dim
#define HH    128         // fc hidden
#define BB    2000        // crystals
#define NCONV 3
#define NM    (NA*MM)     // 1.2M edge rows
#define TWOF  (2*FF)      // 128
#define WF_ROWS (2*FF + NBRF)         // 169
#define WF_STRIDE (WF_ROWS * TWOF)    // 169*128 per layer

#define TILE_E  64                    // edges per GEMM tile
#define NTILES  (NM / TILE_E)         // 18750 exactly
#define NF_STRIDE 72                  // padded edge-stride for NF_s (16B aligned rows)
#define KG_GRID 592                   // 148 SMs * 4

// ---------------- scratch (device globals; no allocation) -------------
__device__ float  g_h[NA * FF];                 // 25.6 MB
__device__ float  g_A[NA * TWOF];               // 51.2 MB  h @ Wf_self
__device__ float  g_P[NA * TWOF];               // 51.2 MB  h @ Wf_nbr
__device__ float  g_G[(size_t)NM * TWOF];       // 614 MB   gated pre-BN
__device__ float  g_summed[NA * FF];            // 25.6 MB
__device__ double g_stat1[2 * TWOF];            // sum / sumsq (128 cols)
__device__ double g_stat2[2 * FF];              // sum / sumsq (64 cols)
__device__ float  g_bn1[2 * TWOF];              // scale(128), shift(128)
__device__ float  g_bn2[2 * FF];                // scale(64), shift(64)
__device__ float  g_pool[BB * FF];
__device__ float  g_cnt[BB];

// ---------------- helpers ----------------
__device__ __forceinline__ float softplusf_(float x) {
    return fmaxf(x, 0.f) + log1pf(__expf(-fabsf(x)));
}
__device__ __forceinline__ float sigmoidf_(float x) {
    return 1.f / (1.f + __expf(-x));
}

// ---------------- kernels ----------------

// h = atom_fea @ W_emb + b_emb    [NA,92]@[92,64]
__global__ void k_embed(const float* __restrict__ atom,
                        const float* __restrict__ W,
                        const float* __restrict__ b) {
    __shared__ float sW[ORIG * FF];
    __shared__ float sb[FF];
    __shared__ float sa[ORIG];
    int tid = threadIdx.x;            // 64 threads
    for (int i = tid; i < ORIG * FF; i += 64) sW[i] = W[i];
    if (tid < FF) sb[tid] = b[tid];
    __syncthreads();
    for (int r = 0; r < 64; r++) {
        int row = blockIdx.x * 64 + r;
        if (row >= NA) break;                    // uniform per block
        __syncthreads();
        for (int i = tid; i < ORIG; i += 64) sa[i] = atom[row * ORIG + i];
        __syncthreads();
        float acc = sb[tid];
        #pragma unroll 4
        for (int k = 0; k < ORIG; k++) acc = fmaf(sa[k], sW[k * FF + tid], acc);
        g_h[row * FF + tid] = acc;
    }
}

// A[n,j] = sum_k h[n,k] * Wf[k,j];  P[n,j] = sum_k h[n,k] * Wf[64+k,j]
__global__ void __launch_bounds__(128) k_AP(const float* __restrict__ Wf) {
    __shared__ float sh[4][FF];
    int j = threadIdx.x;              // 0..127
    int n0 = blockIdx.x * 4;
    for (int i = j; i < 4 * FF; i += 128) {
        int r = i >> 6, k = i & 63;
        sh[r][k] = g_h[(n0 + r) * FF + k];   // NA divisible by 4
    }
    __syncthreads();
    float a0 = 0, a1 = 0, a2 = 0, a3 = 0;
    float p0 = 0, p1 = 0, p2 = 0, p3 = 0;
    #pragma unroll
    for (int k = 0; k < FF; k++) {
        float wa = __ldg(&Wf[k * TWOF + j]);
        float wb = __ldg(&Wf[(FF + k) * TWOF + j]);
        a0 = fmaf(sh[0][k], wa, a0); p0 = fmaf(sh[0][k], wb, p0);
        a1 = fmaf(sh[1][k], wa, a1); p1 = fmaf(sh[1][k], wb, p1);
        a2 = fmaf(sh[2][k], wa, a2); p2 = fmaf(sh[2][k], wb, p2);
        a3 = fmaf(sh[3][k], wa, a3); p3 = fmaf(sh[3][k], wb, p3);
    }
    g_A[(n0 + 0) * TWOF + j] = a0;  g_P[(n0 + 0) * TWOF + j] = p0;
    g_A[(n0 + 1) * TWOF + j] = a1;  g_P[(n0 + 1) * TWOF + j] = p1;
    g_A[(n0 + 2) * TWOF + j] = a2;  g_P[(n0 + 2) * TWOF + j] = p2;
    g_A[(n0 + 3) * TWOF + j] = a3;  g_P[(n0 + 3) * TWOF + j] = p3;
}

__global__ void k_zero_stats() {
    int i = threadIdx.x;
    if (i < 2 * TWOF) g_stat1[i] = 0.0;
    if (i < 2 * FF)   g_stat2[i] = 0.0;
}

// ---------------------------------------------------------------------
// k_G2: register-blocked tiled GEMM over edges.
//   G[e, j] = NF[e,:]@Wnf[:,j] + A[e/12, j] + P[idx[e], j] + bf[j]
// Tile: 64 edges x 128 cols, K=41. 128 threads = 8 (edge grp) x 16 (col grp),
// 8x8 register micro-tile. Weights staged once per block; blocks grid-stride
// over tiles. Fused column sum/sumsq stats (fp32 regs -> shared -> fp64 atomics).
// ---------------------------------------------------------------------
__global__ void __launch_bounds__(128) k_G2(const float* __restrict__ nbr_fea,
                                            const int*   __restrict__ idx,
                                            const float* __restrict__ Wf,
                                            const float* __restrict__ bf) {
    __shared__ float W_s[NBRF * TWOF];          // 41*128 = 21KB
    __shared__ float NF_s[NBRF * NF_STRIDE];    // 41*72  = 11.8KB (reused for reduce)
    int tid = threadIdx.x;
    int tm = tid >> 4;                          // 0..7  edge group
    int tn = tid & 15;                          // 0..15 col group
    int eoff = tm * 8;                          // local edge base
    int joff = tn * 8;                          // col base

    // stage weights once (Wnf rows are contiguous at offset 128*128 in Wf)
    for (int i = tid; i < NBRF * TWOF; i += 128) W_s[i] = __ldg(&Wf[TWOF * TWOF + i]);

    float bfj[8];
    #pragma unroll
    for (int c = 0; c < 8; c++) bfj[c] = __ldg(&bf[joff + c]);

    float st_s[8], st_q[8];
    #pragma unroll
    for (int c = 0; c < 8; c++) { st_s[c] = 0.f; st_q[c] = 0.f; }

    for (int t = blockIdx.x; t < NTILES; t += gridDim.x) {
        size_t e0 = (size_t)t * TILE_E;
        __syncthreads();   // protect NF_s reads of previous tile
        // load NF tile transposed: NF_s[k][e_local]
        for (int i = tid; i < TILE_E * NBRF; i += 128) {
            int e = i / NBRF;
            int k = i - e * NBRF;
            NF_s[k * NF_STRIDE + e] = nbr_fea[e0 * NBRF + i];
        }
        __syncthreads();

        float acc[8][8];
        #pragma unroll
        for (int r = 0; r < 8; r++)
            #pragma unroll
            for (int c = 0; c < 8; c++) acc[r][c] = 0.f;

        #pragma unroll 1
        for (int k = 0; k < NBRF; k++) {
            float4 a0 = *(const float4*)&NF_s[k * NF_STRIDE + eoff];
            float4 a1 = *(const float4*)&NF_s[k * NF_STRIDE + eoff + 4];
            float4 b0 = *(const float4*)&W_s[k * TWOF + joff];
            float4 b1 = *(const float4*)&W_s[k * TWOF + joff + 4];
            float a[8] = {a0.x, a0.y, a0.z, a0.w, a1.x, a1.y, a1.z, a1.w};
            float b[8] = {b0.x, b0.y, b0.z, b0.w, b1.x, b1.y, b1.z, b1.w};
            #pragma unroll
            for (int r = 0; r < 8; r++)
                #pragma unroll
                for (int c = 0; c < 8; c++)
                    acc[r][c] = fmaf(a[r], b[c], acc[r][c]);
        }

        // epilogue: + A[n] + P[idx] + bias, store, stats
        #pragma unroll
        for (int r = 0; r < 8; r++) {
            int e  = (int)e0 + eoff + r;
            int n  = e / MM;
            int nb = __ldg(&idx[e]);
            float4 A0 = __ldg((const float4*)&g_A[(size_t)n  * TWOF + joff]);
            float4 A1 = __ldg((const float4*)&g_A[(size_t)n  * TWOF + joff + 4]);
            float4 P0 = __ldg((const float4*)&g_P[(size_t)nb * TWOF + joff]);
            float4 P1 = __ldg((const float4*)&g_P[(size_t)nb * TWOF + joff + 4]);
            float ad[8] = {A0.x + P0.x, A0.y + P0.y, A0.z + P0.z, A0.w + P0.w,
                           A1.x + P1.x, A1.y + P1.y, A1.z + P1.z, A1.w + P1.w};
            float o[8];
            #pragma unroll
            for (int c = 0; c < 8; c++) {
                o[c] = acc[r][c] + ad[c] + bfj[c];
                st_s[c] += o[c];
                st_q[c] = fmaf(o[c], o[c], st_q[c]);
            }
            float* dst = &g_G[(size_t)e * TWOF + joff];
            *(float4*)dst       = make_float4(o[0], o[1], o[2], o[3]);
            *(float4*)(dst + 4) = make_float4(o[4], o[5], o[6], o[7]);
        }
    }

    // block-level stat reduction through shared (reuse NF_s), then fp64 atomics
    float* red = NF_s;   // need 8*128 = 1024 floats, NF_s has 2952
    __syncthreads();
    #pragma unroll
    for (int c = 0; c < 8; c++) red[tm * TWOF + joff + c] = st_s[c];
    __syncthreads();
    {
        double s = 0.0;
        #pragma unroll
        for (int g = 0; g < 8; g++) s += (double)red[g * TWOF + tid];
        atomicAdd(&g_stat1[tid], s);
    }
    __syncthreads();
    #pragma unroll
    for (int c = 0; c < 8; c++) red[tm * TWOF + joff + c] = st_q[c];
    __syncthreads();
    {
        double q = 0.0;
        #pragma unroll
        for (int g = 0; g < 8; g++) q += (double)red[g * TWOF + tid];
        atomicAdd(&g_stat1[TWOF + tid], q);
    }
}

// BN affine params from accumulated stats.
__global__ void k_bnparam(int which,
                          const float* __restrict__ gamma,
                          const float* __restrict__ beta) {
    int j = threadIdx.x;
    if (which == 0) {
        if (j >= TWOF) return;
        double inv = 1.0 / (double)NM;
        double mu = g_stat1[j] * inv;
        double var = g_stat1[TWOF + j] * inv - mu * mu;
        float sc = gamma[j] * rsqrtf((float)var + 1e-5f);
        g_bn1[j] = sc;
        g_bn1[TWOF + j] = beta[j] - (float)mu * sc;
    } else {
        if (j >= FF) return;
        double inv = 1.0 / (double)NA;
        double mu = g_stat2[j] * inv;
        double var = g_stat2[FF + j] * inv - mu * mu;
        float sc = gamma[j] * rsqrtf((float)var + 1e-5f);
        g_bn2[j] = sc;
        g_bn2[FF + j] = beta[j] - (float)mu * sc;
    }
}

// summed[n,j] = sum_m sigmoid(bn(Gf)) * softplus(bn(Gc)); + stats over n.
__global__ void __launch_bounds__(256) k_S() {
    int tid = threadIdx.x;
    int j = tid & 63;
    int grp = tid >> 6;                       // 0..3
    float scf = g_bn1[j],        shf = g_bn1[TWOF + j];
    float scc = g_bn1[FF + j],   shc = g_bn1[TWOF + FF + j];
    float s = 0.f, s2 = 0.f;
    int nBase = blockIdx.x * 64 + grp * 16;
    for (int t = 0; t < 16; t++) {
        int n = nBase + t;
        if (n >= NA) break;                   // uniform within 2-warp group
        float acc = 0.f;
        size_t r0 = (size_t)n * MM;
        for (int m = 0; m < MM; m++) {
            const float* gr = g_G + (r0 + m) * TWOF;
            float xf = fmaf(scf, __ldg(&gr[j]), shf);
            float xc = fmaf(scc, __ldg(&gr[FF + j]), shc);
            acc = fmaf(sigmoidf_(xf), softplusf_(xc), acc);
        }
        g_summed[n * FF + j] = acc;
        s += acc;
        s2 = fmaf(acc, acc, s2);
    }
    atomicAdd(&g_stat2[j], (double)s);
    atomicAdd(&g_stat2[FF + j], (double)s2);
}

// h = softplus(h + bn2(summed))
__global__ void k_H() {
    int i = blockIdx.x * blockDim.x + threadIdx.x;
    if (i >= NA * FF) return;
    int j = i & 63;
    float x = fmaf(g_bn2[j], g_summed[i], g_bn2[FF + j]);
    g_h[i] = softplusf_(g_h[i] + x);
}

__global__ void k_zero_pool() {
    int i = blockIdx.x * 256 + threadIdx.x;
    if (i < BB * FF) g_pool[i] = 0.f;
    if (i < BB) g_cnt[i] = 0.f;
}

__global__ void k_pool(const int* __restrict__ cid) {
    int n = blockIdx.x;
    int c = cid[n];
    atomicAdd(&g_pool[c * FF + threadIdx.x], g_h[n * FF + threadIdx.x]);
    if (threadIdx.x == 0) atomicAdd(&g_cnt[c], 1.f);
}

// crys = pool/cnt; out[b] = softplus(crys@W_fc + b_fc) @ W_out + b_out
__global__ void k_head(const float* __restrict__ Wfc,
                       const float* __restrict__ bfc,
                       const float* __restrict__ Wout,
                       const float* __restrict__ bout,
                       float* __restrict__ out) {
    int b = blockIdx.x;
    int t = threadIdx.x;                      // 128
    __shared__ float sc[FF];
    __shared__ float red[HH];
    float inv = 1.f / fmaxf(g_cnt[b], 1.f);
    if (t < FF) sc[t] = g_pool[b * FF + t] * inv;
    __syncthreads();
    float acc = bfc[t];
    #pragma unroll
    for (int k = 0; k < FF; k++) acc = fmaf(sc[k], __ldg(&Wfc[k * HH + t]), acc);
    red[t] = softplusf_(acc) * __ldg(&Wout[t]);
    __syncthreads();
    for (int off = 64; off > 0; off >>= 1) {
        if (t < off) red[t] += red[t + off];
        __syncthreads();
    }
    if (t == 0) out[b] = red[0] + bout[0];
}

// ---------------- launch ----------------
extern "C" void kernel_launch(void* const* d_in, const int* in_sizes, int n_in,
                              void* d_out, int out_size) {
    const float* atom_fea = (const float*)d_in[0];
    const float* nbr_fea  = (const float*)d_in[1];
    const int*   nbr_idx  = (const int*)d_in[2];
    const int*   cid      = (const int*)d_in[3];
    int o = (n_in >= 17 && in_sizes[4] == 1) ? 1 : 0;
    const float* W_emb = (const float*)d_in[4 + o];
    const float* b_emb = (const float*)d_in[5 + o];
    const float* Wf    = (const float*)d_in[6 + o];
    const float* bf    = (const float*)d_in[7 + o];
    const float* g1    = (const float*)d_in[8 + o];
    const float* b1    = (const float*)d_in[9 + o];
    const float* g2    = (const float*)d_in[10 + o];
    const float* b2    = (const float*)d_in[11 + o];
    const float* W_fc  = (const float*)d_in[12 + o];
    const float* b_fc  = (const float*)d_in[13 + o];
    const float* W_out = (const float*)d_in[14 + o];
    const float* b_out = (const float*)d_in[15 + o];
    float* out = (float*)d_out;

    k_embed<<<(NA + 63) / 64, 64>>>(atom_fea, W_emb, b_emb);

    for (int l = 0; l < NCONV; l++) {
        const float* Wfl = Wf + l * WF_STRIDE;
        const float* bfl = bf + l * TWOF;
        const float* g1l = g1 + l * TWOF;
        const float* b1l = b1 + l * TWOF;
        const float* g2l = g2 + l * FF;
        const float* b2l = b2 + l * FF;

        k_zero_stats<<<1, 256>>>();
        k_AP<<<NA / 4, 128>>>(Wfl);
        k_G2<<<KG_GRID, 128>>>(nbr_fea, nbr_idx, Wfl, bfl);
        k_bnparam<<<1, 128>>>(0, g1l, b1l);
        k_S<<<(NA + 63) / 64, 256>>>();
        k_bnparam<<<1, 64>>>(1, g2l, b2l);
        k_H<<<(NA * FF) / 256, 256>>>();
    }

    k_zero_pool<<<(BB * FF + 255) / 256, 256>>>();
    k_pool<<<NA, FF>>>(cid);
    k_head<<<BB, HH>>>(W_fc, b_fc, W_out, b_out, out);
}

// round 5
// speedup vs baseline: 1.1507x; 1.0476x over previous
#include <cuda_runtime.h>
#include <math.h>
#include <stdint.h>

// ---------------- problem dims (fixed by setup_inputs) ----------------
#define NA    100000      // atoms
#define MM    12          // neighbors per atom
#define ORIG  92          // input atom feature dim
#define NBRF  41          // neighbor (bond) feature dim
#define FF    64          // hidden feature dim
#define HH    128         // fc hidden
#define BB    2000        // crystals
#define NCONV 3
#define NM    (NA*MM)     // 1.2M edge rows
#define TWOF  (2*FF)      // 128
#define WF_ROWS (2*FF + NBRF)         // 169
#define WF_STRIDE (WF_ROWS * TWOF)    // 169*128 per layer

#define TILE_E  64                    // edges per GEMM tile
#define NTILES  (NM / TILE_E)         // 18750 exactly
#define KPAD    48                    // K padded to mult of 8
#define KSTEPS  6
#define NFS     49                    // padded k-stride for A staging
#define CSS     130                   // padded col-stride for C staging (32 rows)
#define KG_GRID 444                   // 148 SMs * 3

// ---------------- scratch (device globals; no allocation) -------------
__device__ float  g_h[NA * FF];                 // 25.6 MB
__device__ float  g_A[NA * TWOF];               // 51.2 MB  h @ Wf_self
__device__ float  g_P[NA * TWOF];               // 51.2 MB  h @ Wf_nbr
__device__ float  g_G[(size_t)NM * TWOF];       // 614 MB   gated pre-BN
__device__ float  g_summed[NA * FF];            // 25.6 MB
__device__ double g_stat1[2 * TWOF];            // sum / sumsq (128 cols)
__device__ double g_stat2[2 * FF];              // sum / sumsq (64 cols)
__device__ float  g_bn1[2 * TWOF];              // scale(128), shift(128)
__device__ float  g_bn2[2 * FF];                // scale(64), shift(64)
__device__ float  g_pool[BB * FF];
__device__ float  g_cnt[BB];

// ---------------- helpers ----------------
__device__ __forceinline__ float softplusf_(float x) {
    return fmaxf(x, 0.f) + log1pf(__expf(-fabsf(x)));
}
__device__ __forceinline__ float sigmoidf_(float x) {
    return 1.f / (1.f + __expf(-x));
}
__device__ __forceinline__ uint32_t f2tf32(float x) {
    uint32_t r;
    asm("cvt.rna.tf32.f32 %0, %1;" : "=r"(r) : "f"(x));
    return r;
}
#define MMA_TF32(c0,c1,c2,c3,a0,a1,a2,a3,b0,b1) \
    asm volatile("mma.sync.aligned.m16n8k8.row.col.f32.tf32.tf32.f32 " \
        "{%0,%1,%2,%3},{%4,%5,%6,%7},{%8,%9},{%0,%1,%2,%3};" \
        : "+f"(c0), "+f"(c1), "+f"(c2), "+f"(c3) \
        : "r"(a0), "r"(a1), "r"(a2), "r"(a3), "r"(b0), "r"(b1))

// ---------------- kernels ----------------

// h = atom_fea @ W_emb + b_emb    [NA,92]@[92,64]
__global__ void k_embed(const float* __restrict__ atom,
                        const float* __restrict__ W,
                        const float* __restrict__ b) {
    __shared__ float sW[ORIG * FF];
    __shared__ float sb[FF];
    __shared__ float sa[ORIG];
    int tid = threadIdx.x;            // 64 threads
    for (int i = tid; i < ORIG * FF; i += 64) sW[i] = W[i];
    if (tid < FF) sb[tid] = b[tid];
    __syncthreads();
    for (int r = 0; r < 64; r++) {
        int row = blockIdx.x * 64 + r;
        if (row >= NA) break;                    // uniform per block
        __syncthreads();
        for (int i = tid; i < ORIG; i += 64) sa[i] = atom[row * ORIG + i];
        __syncthreads();
        float acc = sb[tid];
        #pragma unroll 4
        for (int k = 0; k < ORIG; k++) acc = fmaf(sa[k], sW[k * FF + tid], acc);
        g_h[row * FF + tid] = acc;
    }
}

// A[n,j] = sum_k h[n,k] * Wf[k,j];  P[n,j] = sum_k h[n,k] * Wf[64+k,j]
__global__ void __launch_bounds__(128) k_AP(const float* __restrict__ Wf) {
    __shared__ float sh[4][FF];
    int j = threadIdx.x;              // 0..127
    int n0 = blockIdx.x * 4;
    for (int i = j; i < 4 * FF; i += 128) {
        int r = i >> 6, k = i & 63;
        sh[r][k] = g_h[(n0 + r) * FF + k];   // NA divisible by 4
    }
    __syncthreads();
    float a0 = 0, a1 = 0, a2 = 0, a3 = 0;
    float p0 = 0, p1 = 0, p2 = 0, p3 = 0;
    #pragma unroll
    for (int k = 0; k < FF; k++) {
        float wa = __ldg(&Wf[k * TWOF + j]);
        float wb = __ldg(&Wf[(FF + k) * TWOF + j]);
        a0 = fmaf(sh[0][k], wa, a0); p0 = fmaf(sh[0][k], wb, p0);
        a1 = fmaf(sh[1][k], wa, a1); p1 = fmaf(sh[1][k], wb, p1);
        a2 = fmaf(sh[2][k], wa, a2); p2 = fmaf(sh[2][k], wb, p2);
        a3 = fmaf(sh[3][k], wa, a3); p3 = fmaf(sh[3][k], wb, p3);
    }
    g_A[(n0 + 0) * TWOF + j] = a0;  g_P[(n0 + 0) * TWOF + j] = p0;
    g_A[(n0 + 1) * TWOF + j] = a1;  g_P[(n0 + 1) * TWOF + j] = p1;
    g_A[(n0 + 2) * TWOF + j] = a2;  g_P[(n0 + 2) * TWOF + j] = p2;
    g_A[(n0 + 3) * TWOF + j] = a3;  g_P[(n0 + 3) * TWOF + j] = p3;
}

__global__ void k_zero_stats() {
    int i = threadIdx.x;
    if (i < 2 * TWOF) g_stat1[i] = 0.0;
    if (i < 2 * FF)   g_stat2[i] = 0.0;
}

// ---------------------------------------------------------------------
// k_G3: tf32 tensor-core tiled GEMM over edges.
//   G[e, j] = NF[e,:]@Wnf[:,j] + A[e/12, j] + P[idx[e], j] + bf[j]
// Tile 64 edges x 128 cols, K padded 41->48. 128 threads = 4 warps,
// warp w computes rows 16w..16w+15 via 16 n-tiles of m16n8k8 tf32 mma.
// A-staging (U) and C-staging (Cs) share one smem region — lifetimes are
// disjoint (separated by the post-MMA barrier). Total smem ~41 KB < 48 KB.
// Epilogue: thread-per-column remap for coalesced A/P gather, g_G store,
// and fused per-column BN stats.
// ---------------------------------------------------------------------
__global__ void __launch_bounds__(128) k_G3(const float* __restrict__ nbr_fea,
                                            const int*   __restrict__ idx,
                                            const float* __restrict__ Wf,
                                            const float* __restrict__ bf) {
    __shared__ uint2 Wp[KSTEPS * 16 * 32];        // packed B frags: 24.0 KB
    __shared__ float Cs[32 * CSS];                // 16.25 KB; aliased by U below
    __shared__ int sidx[TILE_E];
    uint32_t* U = (uint32_t*)Cs;                  // TILE_E*NFS = 3136 <= 32*CSS = 4160

    int tid  = threadIdx.x;
    int lane = tid & 31;
    int warp = tid >> 5;
    int m0   = warp * 16;
    int r    = lane >> 2;
    int cq   = lane & 3;

    // ---- pack B fragments once per block ----
    // m16n8k8 B frag: b0 at (k=lane%4, n=lane/4), b1 at (k=lane%4+4, n=lane/4)
    for (int i = tid; i < KSTEPS * 16 * 32; i += 128) {
        int ks = i >> 9;
        int rem = i & 511;
        int nt = rem >> 5;
        int ln = rem & 31;
        int col = nt * 8 + (ln >> 2);
        int k0 = ks * 8 + (ln & 3);
        float w0 = (k0     < NBRF) ? __ldg(&Wf[(TWOF + k0    ) * TWOF + col]) : 0.f;
        float w1 = (k0 + 4 < NBRF) ? __ldg(&Wf[(TWOF + k0 + 4) * TWOF + col]) : 0.f;
        Wp[i] = make_uint2(f2tf32(w0), f2tf32(w1));
    }
    float bfj = __ldg(&bf[tid]);

    double ds = 0.0, dq = 0.0;   // per-thread (= per-column) fp64 stat accums

    for (int t = blockIdx.x; t < NTILES; t += gridDim.x) {
        int e0 = t * TILE_E;
        __syncthreads();                           // U/Cs reuse guard (also covers Wp 1st use)
        // ---- stage NF tile as tf32 (rows x 49, pad k=41..47 zeroed) ----
        for (int i = tid; i < TILE_E * NBRF; i += 128) {
            int e = i / NBRF;
            int k = i - e * NBRF;
            U[e * NFS + k] = f2tf32(nbr_fea[(size_t)e0 * NBRF + i]);
        }
        for (int i = tid; i < TILE_E * (KPAD - NBRF); i += 128) {
            int e = i / (KPAD - NBRF);
            int k = NBRF + (i - e * (KPAD - NBRF));
            U[e * NFS + k] = 0;
        }
        if (tid < TILE_E) sidx[tid] = idx[e0 + tid];
        __syncthreads();

        // ---- MMA phase ----
        float acc[16][4];
        #pragma unroll
        for (int nt = 0; nt < 16; nt++)
            #pragma unroll
            for (int i = 0; i < 4; i++) acc[nt][i] = 0.f;

        #pragma unroll
        for (int ks = 0; ks < KSTEPS; ks++) {
            uint32_t a0 = U[(m0 + r    ) * NFS + ks * 8 + cq    ];
            uint32_t a1 = U[(m0 + r + 8) * NFS + ks * 8 + cq    ];
            uint32_t a2 = U[(m0 + r    ) * NFS + ks * 8 + cq + 4];
            uint32_t a3 = U[(m0 + r + 8) * NFS + ks * 8 + cq + 4];
            #pragma unroll
            for (int nt = 0; nt < 16; nt++) {
                uint2 b = Wp[(ks * 16 + nt) * 32 + lane];
                MMA_TF32(acc[nt][0], acc[nt][1], acc[nt][2], acc[nt][3],
                         a0, a1, a2, a3, b.x, b.y);
            }
        }
        __syncthreads();                           // done reading U; Cs may be written

        // ---- two half-tiles: stage C, then thread-per-column epilogue ----
        #pragma unroll
        for (int h = 0; h < 2; h++) {
            if ((warp >> 1) == h) {                // warps 2h, 2h+1 own these rows
                int rl = m0 - h * 32 + r;          // 0..7 or 16..23 within half
                #pragma unroll
                for (int nt = 0; nt < 16; nt++) {
                    int jc = nt * 8 + 2 * cq;
                    *(float2*)&Cs[(rl    ) * CSS + jc] = make_float2(acc[nt][0], acc[nt][1]);
                    *(float2*)&Cs[(rl + 8) * CSS + jc] = make_float2(acc[nt][2], acc[nt][3]);
                }
            }
            __syncthreads();
            // thread tid owns column j = tid over 32 edges
            int eg0 = e0 + h * 32;
            int n   = eg0 / MM;
            int rem = eg0 - n * MM;
            float ts = 0.f, tq = 0.f;
            #pragma unroll 4
            for (int e = 0; e < 32; e++) {
                int nb = sidx[h * 32 + e];
                float val = Cs[e * CSS + tid]
                          + __ldg(&g_A[(size_t)n  * TWOF + tid])
                          + __ldg(&g_P[(size_t)nb * TWOF + tid])
                          + bfj;
                ts += val;
                tq = fmaf(val, val, tq);
                g_G[(size_t)(eg0 + e) * TWOF + tid] = val;
                if (++rem == MM) { rem = 0; n++; }
            }
            ds += (double)ts;
            dq += (double)tq;
            __syncthreads();
        }
    }

    atomicAdd(&g_stat1[tid],        ds);
    atomicAdd(&g_stat1[TWOF + tid], dq);
}

// BN affine params from accumulated stats.
__global__ void k_bnparam(int which,
                          const float* __restrict__ gamma,
                          const float* __restrict__ beta) {
    int j = threadIdx.x;
    if (which == 0) {
        if (j >= TWOF) return;
        double inv = 1.0 / (double)NM;
        double mu = g_stat1[j] * inv;
        double var = g_stat1[TWOF + j] * inv - mu * mu;
        float sc = gamma[j] * rsqrtf((float)var + 1e-5f);
        g_bn1[j] = sc;
        g_bn1[TWOF + j] = beta[j] - (float)mu * sc;
    } else {
        if (j >= FF) return;
        double inv = 1.0 / (double)NA;
        double mu = g_stat2[j] * inv;
        double var = g_stat2[FF + j] * inv - mu * mu;
        float sc = gamma[j] * rsqrtf((float)var + 1e-5f);
        g_bn2[j] = sc;
        g_bn2[FF + j] = beta[j] - (float)mu * sc;
    }
}

// summed[n,j] = sum_m sigmoid(bn(Gf)) * softplus(bn(Gc)); + stats over n.
__global__ void __launch_bounds__(256) k_S() {
    int tid = threadIdx.x;
    int j = tid & 63;
    int grp = tid >> 6;                       // 0..3
    float scf = g_bn1[j],        shf = g_bn1[TWOF + j];
    float scc = g_bn1[FF + j],   shc = g_bn1[TWOF + FF + j];
    float s = 0.f, s2 = 0.f;
    int nBase = blockIdx.x * 64 + grp * 16;
    for (int t = 0; t < 16; t++) {
        int n = nBase + t;
        if (n >= NA) break;                   // uniform within 2-warp group
        float acc = 0.f;
        size_t r0 = (size_t)n * MM;
        for (int m = 0; m < MM; m++) {
            const float* gr = g_G + (r0 + m) * TWOF;
            float xf = fmaf(scf, __ldg(&gr[j]), shf);
            float xc = fmaf(scc, __ldg(&gr[FF + j]), shc);
            acc = fmaf(sigmoidf_(xf), softplusf_(xc), acc);
        }
        g_summed[n * FF + j] = acc;
        s += acc;
        s2 = fmaf(acc, acc, s2);
    }
    atomicAdd(&g_stat2[j], (double)s);
    atomicAdd(&g_stat2[FF + j], (double)s2);
}

// h = softplus(h + bn2(summed))
__global__ void k_H() {
    int i = blockIdx.x * blockDim.x + threadIdx.x;
    if (i >= NA * FF) return;
    int j = i & 63;
    float x = fmaf(g_bn2[j], g_summed[i], g_bn2[FF + j]);
    g_h[i] = softplusf_(g_h[i] + x);
}

__global__ void k_zero_pool() {
    int i = blockIdx.x * 256 + threadIdx.x;
    if (i < BB * FF) g_pool[i] = 0.f;
    if (i < BB) g_cnt[i] = 0.f;
}

__global__ void k_pool(const int* __restrict__ cid) {
    int n = blockIdx.x;
    int c = cid[n];
    atomicAdd(&g_pool[c * FF + threadIdx.x], g_h[n * FF + threadIdx.x]);
    if (threadIdx.x == 0) atomicAdd(&g_cnt[c], 1.f);
}

// crys = pool/cnt; out[b] = softplus(crys@W_fc + b_fc) @ W_out + b_out
__global__ void k_head(const float* __restrict__ Wfc,
                       const float* __restrict__ bfc,
                       const float* __restrict__ Wout,
                       const float* __restrict__ bout,
                       float* __restrict__ out) {
    int b = blockIdx.x;
    int t = threadIdx.x;                      // 128
    __shared__ float sc[FF];
    __shared__ float red[HH];
    float inv = 1.f / fmaxf(g_cnt[b], 1.f);
    if (t < FF) sc[t] = g_pool[b * FF + t] * inv;
    __syncthreads();
    float acc = bfc[t];
    #pragma unroll
    for (int k = 0; k < FF; k++) acc = fmaf(sc[k], __ldg(&Wfc[k * HH + t]), acc);
    red[t] = softplusf_(acc) * __ldg(&Wout[t]);
    __syncthreads();
    for (int off = 64; off > 0; off >>= 1) {
        if (t < off) red[t] += red[t + off];
        __syncthreads();
    }
    if (t == 0) out[b] = red[0] + bout[0];
}

// ---------------- launch ----------------
extern "C" void kernel_launch(void* const* d_in, const int* in_sizes, int n_in,
                              void* d_out, int out_size) {
    const float* atom_fea = (const float*)d_in[0];
    const float* nbr_fea  = (const float*)d_in[1];
    const int*   nbr_idx  = (const int*)d_in[2];
    const int*   cid      = (const int*)d_in[3];
    int o = (n_in >= 17 && in_sizes[4] == 1) ? 1 : 0;
    const float* W_emb = (const float*)d_in[4 + o];
    const float* b_emb = (const float*)d_in[5 + o];
    const float* Wf    = (const float*)d_in[6 + o];
    const float* bf    = (const float*)d_in[7 + o];
    const float* g1    = (const float*)d_in[8 + o];
    const float* b1    = (const float*)d_in[9 + o];
    const float* g2    = (const float*)d_in[10 + o];
    const float* b2    = (const float*)d_in[11 + o];
    const float* W_fc  = (const float*)d_in[12 + o];
    const float* b_fc  = (const float*)d_in[13 + o];
    const float* W_out = (const float*)d_in[14 + o];
    const float* b_out = (const float*)d_in[15 + o];
    float* out = (float*)d_out;

    k_embed<<<(NA + 63) / 64, 64>>>(atom_fea, W_emb, b_emb);

    for (int l = 0; l < NCONV; l++) {
        const float* Wfl = Wf + l * WF_STRIDE;
        const float* bfl = bf + l * TWOF;
        const float* g1l = g1 + l * TWOF;
        const float* b1l = b1 + l * TWOF;
        const float* g2l = g2 + l * FF;
        const float* b2l = b2 + l * FF;

        k_zero_stats<<<1, 256>>>();
        k_AP<<<NA / 4, 128>>>(Wfl);
        k_G3<<<KG_GRID, 128>>>(nbr_fea, nbr_idx, Wfl, bfl);
        k_bnparam<<<1, 128>>>(0, g1l, b1l);
        k_S<<<(NA + 63) / 64, 256>>>();
        k_bnparam<<<1, 64>>>(1, g2l, b2l);
        k_H<<<(NA * FF) / 256, 256>>>();
    }

    k_zero_pool<<<(BB * FF + 255) / 256, 256>>>();
    k_pool<<<NA, FF>>>(cid);
    k_head<<<BB, HH>>>(W_fc, b_fc, W_out, b_out, out);
}

// round 7
// speedup vs baseline: 1.1786x; 1.0242x over previous
#include <cuda_runtime.h>
#include <math.h>
#include <stdint.h>

// ---------------- problem dims (fixed by setup_inputs) ----------------
#define NA    100000      // atoms
#define MM    12          // neighbors per atom
#define ORIG  92          // input atom feature dim
#define NBRF  41          // neighbor (bond) feature dim
#define FF    64          // hidden feature dim
#define HH    128         // fc hidden
#define BB    2000        // crystals
#define NCONV 3
#define NM    (NA*MM)     // 1.2M edge rows
#define TWOF  (2*FF)      // 128
#define WF_ROWS (2*FF + NBRF)         // 169
#define WF_STRIDE (WF_ROWS * TWOF)    // 169*128 per layer

#define TILE_E  64                    // edges per GEMM tile
#define NTILES  (NM / TILE_E)         // 18750 exactly
#define KPAD    48                    // K padded to mult of 8
#define KSTEPS  6
#define NFS     49                    // padded k-stride for A staging
#define CSS     130                   // padded col-stride for C staging (32 rows)
#define KG_GRID 740                   // 148 SMs * 5 (smem allows 5 blocks/SM)

// ---------------- scratch (device globals; no allocation) -------------
__device__ float  g_h[NA * FF];                 // 25.6 MB
__device__ float  g_A[NA * TWOF];               // 51.2 MB  h @ Wf_self
__device__ float  g_P[NA * TWOF];               // 51.2 MB  h @ Wf_nbr
__device__ float  g_summed[NA * FF];            // 25.6 MB (atomic-accumulated)
__device__ double g_stat1[2 * TWOF];            // sum / sumsq (128 cols)
__device__ double g_stat2[2 * FF];              // sum / sumsq (64 cols)
__device__ float  g_bn1[2 * TWOF];              // scale(128), shift(128)
__device__ float  g_bn2[2 * FF];                // scale(64), shift(64)
__device__ float  g_pool[BB * FF];
__device__ float  g_cnt[BB];

// ---------------- helpers ----------------
__device__ __forceinline__ float softplusf_(float x) {
    // stable: max(x,0) + log(1+exp(-|x|)); __logf ok: arg in (1,2]
    return fmaxf(x, 0.f) + __logf(1.f + __expf(-fabsf(x)));
}
__device__ __forceinline__ float sigmoidf_(float x) {
    return 1.f / (1.f + __expf(-x));
}
__device__ __forceinline__ uint32_t f2tf32(float x) {
    uint32_t r;
    asm("cvt.rna.tf32.f32 %0, %1;" : "=r"(r) : "f"(x));
    return r;
}
#define MMA_TF32(c0,c1,c2,c3,a0,a1,a2,a3,b0,b1) \
    asm volatile("mma.sync.aligned.m16n8k8.row.col.f32.tf32.tf32.f32 " \
        "{%0,%1,%2,%3},{%4,%5,%6,%7},{%8,%9},{%0,%1,%2,%3};" \
        : "+f"(c0), "+f"(c1), "+f"(c2), "+f"(c3) \
        : "r"(a0), "r"(a1), "r"(a2), "r"(a3), "r"(b0), "r"(b1))

// Shared GEMM front-end: pack B frags, stage NF tile, run MMAs.
struct TileCtx {
    int tid, lane, warp, m0, r, cq;
};

__device__ __forceinline__ void pack_B(uint2* Wp, const float* __restrict__ Wf, int tid) {
    for (int i = tid; i < KSTEPS * 16 * 32; i += 128) {
        int ks = i >> 9;
        int rem = i & 511;
        int nt = rem >> 5;
        int ln = rem & 31;
        int col = nt * 8 + (ln >> 2);
        int k0 = ks * 8 + (ln & 3);
        float w0 = (k0     < NBRF) ? __ldg(&Wf[(TWOF + k0    ) * TWOF + col]) : 0.f;
        float w1 = (k0 + 4 < NBRF) ? __ldg(&Wf[(TWOF + k0 + 4) * TWOF + col]) : 0.f;
        Wp[i] = make_uint2(f2tf32(w0), f2tf32(w1));
    }
}

__device__ __forceinline__ void stage_NF(uint32_t* U, const float* __restrict__ nbr_fea,
                                         int e0, int tid) {
    for (int i = tid; i < TILE_E * NBRF; i += 128) {
        int e = i / NBRF;
        int k = i - e * NBRF;
        U[e * NFS + k] = f2tf32(nbr_fea[(size_t)e0 * NBRF + i]);
    }
    for (int i = tid; i < TILE_E * (KPAD - NBRF); i += 128) {
        int e = i / (KPAD - NBRF);
        int k = NBRF + (i - e * (KPAD - NBRF));
        U[e * NFS + k] = 0;
    }
}

__device__ __forceinline__ void run_mma(float acc[16][4], const uint32_t* U,
                                        const uint2* Wp, const TileCtx& c) {
    #pragma unroll
    for (int nt = 0; nt < 16; nt++)
        #pragma unroll
        for (int i = 0; i < 4; i++) acc[nt][i] = 0.f;
    #pragma unroll
    for (int ks = 0; ks < KSTEPS; ks++) {
        uint32_t a0 = U[(c.m0 + c.r    ) * NFS + ks * 8 + c.cq    ];
        uint32_t a1 = U[(c.m0 + c.r + 8) * NFS + ks * 8 + c.cq    ];
        uint32_t a2 = U[(c.m0 + c.r    ) * NFS + ks * 8 + c.cq + 4];
        uint32_t a3 = U[(c.m0 + c.r + 8) * NFS + ks * 8 + c.cq + 4];
        #pragma unroll
        for (int nt = 0; nt < 16; nt++) {
            uint2 b = Wp[(ks * 16 + nt) * 32 + c.lane];
            MMA_TF32(acc[nt][0], acc[nt][1], acc[nt][2], acc[nt][3],
                     a0, a1, a2, a3, b.x, b.y);
        }
    }
}

__device__ __forceinline__ void stage_C(float* Cs, const float acc[16][4],
                                        const TileCtx& c, int h) {
    if ((c.warp >> 1) == h) {                // warps 2h, 2h+1 own these rows
        int rl = c.m0 - h * 32 + c.r;        // 0..7 or 16..23 within half
        #pragma unroll
        for (int nt = 0; nt < 16; nt++) {
            int jc = nt * 8 + 2 * c.cq;
            *(float2*)&Cs[(rl    ) * CSS + jc] = make_float2(acc[nt][0], acc[nt][1]);
            *(float2*)&Cs[(rl + 8) * CSS + jc] = make_float2(acc[nt][2], acc[nt][3]);
        }
    }
}

// ---------------- kernels ----------------

// h = atom_fea @ W_emb + b_emb    [NA,92]@[92,64]
__global__ void k_embed(const float* __restrict__ atom,
                        const float* __restrict__ W,
                        const float* __restrict__ b) {
    __shared__ float sW[ORIG * FF];
    __shared__ float sb[FF];
    __shared__ float sa[ORIG];
    int tid = threadIdx.x;            // 64 threads
    for (int i = tid; i < ORIG * FF; i += 64) sW[i] = W[i];
    if (tid < FF) sb[tid] = b[tid];
    __syncthreads();
    for (int r = 0; r < 64; r++) {
        int row = blockIdx.x * 64 + r;
        if (row >= NA) break;                    // uniform per block
        __syncthreads();
        for (int i = tid; i < ORIG; i += 64) sa[i] = atom[row * ORIG + i];
        __syncthreads();
        float acc = sb[tid];
        #pragma unroll 4
        for (int k = 0; k < ORIG; k++) acc = fmaf(sa[k], sW[k * FF + tid], acc);
        g_h[row * FF + tid] = acc;
    }
}

// A[n,j] = sum_k h[n,k] * Wf[k,j];  P[n,j] = sum_k h[n,k] * Wf[64+k,j]
__global__ void __launch_bounds__(128) k_AP(const float* __restrict__ Wf) {
    __shared__ float sh[4][FF];
    int j = threadIdx.x;              // 0..127
    int n0 = blockIdx.x * 4;
    for (int i = j; i < 4 * FF; i += 128) {
        int r = i >> 6, k = i & 63;
        sh[r][k] = g_h[(n0 + r) * FF + k];   // NA divisible by 4
    }
    __syncthreads();
    float a0 = 0, a1 = 0, a2 = 0, a3 = 0;
    float p0 = 0, p1 = 0, p2 = 0, p3 = 0;
    #pragma unroll
    for (int k = 0; k < FF; k++) {
        float wa = __ldg(&Wf[k * TWOF + j]);
        float wb = __ldg(&Wf[(FF + k) * TWOF + j]);
        a0 = fmaf(sh[0][k], wa, a0); p0 = fmaf(sh[0][k], wb, p0);
        a1 = fmaf(sh[1][k], wa, a1); p1 = fmaf(sh[1][k], wb, p1);
        a2 = fmaf(sh[2][k], wa, a2); p2 = fmaf(sh[2][k], wb, p2);
        a3 = fmaf(sh[3][k], wa, a3); p3 = fmaf(sh[3][k], wb, p3);
    }
    g_A[(n0 + 0) * TWOF + j] = a0;  g_P[(n0 + 0) * TWOF + j] = p0;
    g_A[(n0 + 1) * TWOF + j] = a1;  g_P[(n0 + 1) * TWOF + j] = p1;
    g_A[(n0 + 2) * TWOF + j] = a2;  g_P[(n0 + 2) * TWOF + j] = p2;
    g_A[(n0 + 3) * TWOF + j] = a3;  g_P[(n0 + 3) * TWOF + j] = p3;
}

// zero stats + summed accumulator
__global__ void k_zero() {
    int i = blockIdx.x * 256 + threadIdx.x;
    if (i < NA * FF) g_summed[i] = 0.f;
    if (i < 2 * TWOF) g_stat1[i] = 0.0;
    if (i < 2 * FF)   g_stat2[i] = 0.0;
}

// ---------------------------------------------------------------------
// Pass 1: k_Gstat — tf32 GEMM + A/P gather + bias -> column stats ONLY.
// ---------------------------------------------------------------------
__global__ void __launch_bounds__(128, 5) k_Gstat(const float* __restrict__ nbr_fea,
                                                  const int*   __restrict__ idx,
                                                  const float* __restrict__ Wf,
                                                  const float* __restrict__ bf) {
    __shared__ uint2 Wp[KSTEPS * 16 * 32];        // 24.0 KB
    __shared__ float Cs[32 * CSS];                // 16.25 KB; aliased by U
    __shared__ int sidx[TILE_E];
    uint32_t* U = (uint32_t*)Cs;                  // TILE_E*NFS = 3136 <= 4160

    TileCtx c;
    c.tid = threadIdx.x; c.lane = c.tid & 31; c.warp = c.tid >> 5;
    c.m0 = c.warp * 16; c.r = c.lane >> 2; c.cq = c.lane & 3;
    int tid = c.tid;

    pack_B(Wp, Wf, tid);
    float bfj = __ldg(&bf[tid]);

    double ds = 0.0, dq = 0.0;

    for (int t = blockIdx.x; t < NTILES; t += gridDim.x) {
        int e0 = t * TILE_E;
        __syncthreads();
        stage_NF(U, nbr_fea, e0, tid);
        if (tid < TILE_E) sidx[tid] = idx[e0 + tid];
        __syncthreads();

        float acc[16][4];
        run_mma(acc, U, Wp, c);
        __syncthreads();

        #pragma unroll
        for (int h = 0; h < 2; h++) {
            stage_C(Cs, acc, c, h);
            __syncthreads();
            int eg0 = e0 + h * 32;
            int n   = eg0 / MM;
            int rem = eg0 - n * MM;
            float ts = 0.f, tq = 0.f;
            #pragma unroll 8
            for (int e = 0; e < 32; e++) {
                int nb = sidx[h * 32 + e];
                float val = Cs[e * CSS + tid]
                          + __ldg(&g_A[(size_t)n  * TWOF + tid])
                          + __ldg(&g_P[(size_t)nb * TWOF + tid])
                          + bfj;
                ts += val;
                tq = fmaf(val, val, tq);
                if (++rem == MM) { rem = 0; n++; }
            }
            ds += (double)ts;
            dq += (double)tq;
            __syncthreads();
        }
    }

    atomicAdd(&g_stat1[tid],        ds);
    atomicAdd(&g_stat1[TWOF + tid], dq);
}

// ---------------------------------------------------------------------
// Pass 2: k_GS — recompute GEMM, apply bn1, sigmoid*softplus, reduce
// within atoms, atomicAdd into g_summed. Bias folded into BN shift.
// Epilogue threads: j = tid&63 (column), g = tid>>6 (16-edge subgroup).
// ---------------------------------------------------------------------
__global__ void __launch_bounds__(128, 5) k_GS(const float* __restrict__ nbr_fea,
                                               const int*   __restrict__ idx,
                                               const float* __restrict__ Wf,
                                               const float* __restrict__ bf) {
    __shared__ uint2 Wp[KSTEPS * 16 * 32];
    __shared__ float Cs[32 * CSS];
    __shared__ int sidx[TILE_E];
    uint32_t* U = (uint32_t*)Cs;

    TileCtx c;
    c.tid = threadIdx.x; c.lane = c.tid & 31; c.warp = c.tid >> 5;
    c.m0 = c.warp * 16; c.r = c.lane >> 2; c.cq = c.lane & 3;
    int tid = c.tid;

    pack_B(Wp, Wf, tid);

    int j = tid & 63;            // epilogue column (filter col; core col = j+64)
    int g = tid >> 6;            // 0/1 -> edges 16g..16g+15 of the 32-half
    float scf = g_bn1[j];
    float shf = g_bn1[TWOF + j]       + scf * __ldg(&bf[j]);
    float scc = g_bn1[FF + j];
    float shc = g_bn1[TWOF + FF + j]  + scc * __ldg(&bf[FF + j]);

    for (int t = blockIdx.x; t < NTILES; t += gridDim.x) {
        int e0 = t * TILE_E;
        __syncthreads();
        stage_NF(U, nbr_fea, e0, tid);
        if (tid < TILE_E) sidx[tid] = idx[e0 + tid];
        __syncthreads();

        float acc[16][4];
        run_mma(acc, U, Wp, c);
        __syncthreads();

        #pragma unroll
        for (int h = 0; h < 2; h++) {
            stage_C(Cs, acc, c, h);
            __syncthreads();
            // 16 edges per thread: compute gated product, segment-reduce by atom
            int le0 = g * 16;                    // local edge base in half-tile
            int eg  = e0 + h * 32 + le0;         // global edge
            int n   = eg / MM;
            int rem = eg - n * MM;
            float accum = 0.f;
            #pragma unroll 8
            for (int e = 0; e < 16; e++) {
                int le = le0 + e;
                int nb = sidx[h * 32 + le];
                float cf = Cs[le * CSS + j]
                         + __ldg(&g_A[(size_t)n  * TWOF + j])
                         + __ldg(&g_P[(size_t)nb * TWOF + j]);
                float cc = Cs[le * CSS + 64 + j]
                         + __ldg(&g_A[(size_t)n  * TWOF + 64 + j])
                         + __ldg(&g_P[(size_t)nb * TWOF + 64 + j]);
                float xf = fmaf(scf, cf, shf);
                float xc = fmaf(scc, cc, shc);
                accum = fmaf(sigmoidf_(xf), softplusf_(xc), accum);
                if (++rem == MM) {
                    atomicAdd(&g_summed[n * FF + j], accum);
                    accum = 0.f; rem = 0; n++;
                }
            }
            if (rem != 0) atomicAdd(&g_summed[n * FF + j], accum);
            __syncthreads();
        }
    }
}

// stats over g_summed (per column over atoms)
__global__ void __launch_bounds__(256) k_stat2() {
    int tid = threadIdx.x;
    int j = tid & 63;
    int grp = tid >> 6;                       // 0..3
    float s = 0.f, s2 = 0.f;
    int nBase = blockIdx.x * 256 + grp * 64;
    for (int t = 0; t < 64; t++) {
        int n = nBase + t;
        if (n >= NA) break;                   // uniform within group
        float v = g_summed[n * FF + j];
        s += v;
        s2 = fmaf(v, v, s2);
    }
    atomicAdd(&g_stat2[j], (double)s);
    atomicAdd(&g_stat2[FF + j], (double)s2);
}

// BN affine params from accumulated stats.
__global__ void k_bnparam(int which,
                          const float* __restrict__ gamma,
                          const float* __restrict__ beta) {
    int j = threadIdx.x;
    if (which == 0) {
        if (j >= TWOF) return;
        double inv = 1.0 / (double)NM;
        double mu = g_stat1[j] * inv;
        double var = g_stat1[TWOF + j] * inv - mu * mu;
        float sc = gamma[j] * rsqrtf((float)var + 1e-5f);
        g_bn1[j] = sc;
        g_bn1[TWOF + j] = beta[j] - (float)mu * sc;
    } else {
        if (j >= FF) return;
        double inv = 1.0 / (double)NA;
        double mu = g_stat2[j] * inv;
        double var = g_stat2[FF + j] * inv - mu * mu;
        float sc = gamma[j] * rsqrtf((float)var + 1e-5f);
        g_bn2[j] = sc;
        g_bn2[FF + j] = beta[j] - (float)mu * sc;
    }
}

// h = softplus(h + bn2(summed))
__global__ void k_H() {
    int i = blockIdx.x * blockDim.x + threadIdx.x;
    if (i >= NA * FF) return;
    int j = i & 63;
    float x = fmaf(g_bn2[j], g_summed[i], g_bn2[FF + j]);
    g_h[i] = softplusf_(g_h[i] + x);
}

__global__ void k_zero_pool() {
    int i = blockIdx.x * 256 + threadIdx.x;
    if (i < BB * FF) g_pool[i] = 0.f;
    if (i < BB) g_cnt[i] = 0.f;
}

__global__ void k_pool(const int* __restrict__ cid) {
    int n = blockIdx.x;
    int c = cid[n];
    atomicAdd(&g_pool[c * FF + threadIdx.x], g_h[n * FF + threadIdx.x]);
    if (threadIdx.x == 0) atomicAdd(&g_cnt[c], 1.f);
}

// crys = pool/cnt; out[b] = softplus(crys@W_fc + b_fc) @ W_out + b_out
__global__ void k_head(const float* __restrict__ Wfc,
                       const float* __restrict__ bfc,
                       const float* __restrict__ Wout,
                       const float* __restrict__ bout,
                       float* __restrict__ out) {
    int b = blockIdx.x;
    int t = threadIdx.x;                      // 128
    __shared__ float sc[FF];
    __shared__ float red[HH];
    float inv = 1.f / fmaxf(g_cnt[b], 1.f);
    if (t < FF) sc[t] = g_pool[b * FF + t] * inv;
    __syncthreads();
    float acc = bfc[t];
    #pragma unroll
    for (int k = 0; k < FF; k++) acc = fmaf(sc[k], __ldg(&Wfc[k * HH + t]), acc);
    red[t] = softplusf_(acc) * __ldg(&Wout[t]);
    __syncthreads();
    for (int off = 64; off > 0; off >>= 1) {
        if (t < off) red[t] += red[t + off];
        __syncthreads();
    }
    if (t == 0) out[b] = red[0] + bout[0];
}

// ---------------- launch ----------------
extern "C" void kernel_launch(void* const* d_in, const int* in_sizes, int n_in,
                              void* d_out, int out_size) {
    const float* atom_fea = (const float*)d_in[0];
    const float* nbr_fea  = (const float*)d_in[1];
    const int*   nbr_idx  = (const int*)d_in[2];
    const int*   cid      = (const int*)d_in[3];
    int o = (n_in >= 17 && in_sizes[4] == 1) ? 1 : 0;
    const float* W_emb = (const float*)d_in[4 + o];
    const float* b_emb = (const float*)d_in[5 + o];
    const float* Wf    = (const float*)d_in[6 + o];
    const float* bf    = (const float*)d_in[7 + o];
    const float* g1    = (const float*)d_in[8 + o];
    const float* b1    = (const float*)d_in[9 + o];
    const float* g2    = (const float*)d_in[10 + o];
    const float* b2    = (const float*)d_in[11 + o];
    const float* W_fc  = (const float*)d_in[12 + o];
    const float* b_fc  = (const float*)d_in[13 + o];
    const float* W_out = (const float*)d_in[14 + o];
    const float* b_out = (const float*)d_in[15 + o];
    float* out = (float*)d_out;

    k_embed<<<(NA + 63) / 64, 64>>>(atom_fea, W_emb, b_emb);

    for (int l = 0; l < NCONV; l++) {
        const float* Wfl = Wf + l * WF_STRIDE;
        const float* bfl = bf + l * TWOF;
        const float* g1l = g1 + l * TWOF;
        const float* b1l = b1 + l * TWOF;
        const float* g2l = g2 + l * FF;
        const float* b2l = b2 + l * FF;

        k_zero<<<(NA * FF + 255) / 256, 256>>>();
        k_AP<<<NA / 4, 128>>>(Wfl);
        k_Gstat<<<KG_GRID, 128>>>(nbr_fea, nbr_idx, Wfl, bfl);
        k_bnparam<<<1, 128>>>(0, g1l, b1l);
        k_GS<<<KG_GRID, 128>>>(nbr_fea, nbr_idx, Wfl, bfl);
        k_stat2<<<(NA + 255) / 256, 256>>>();
        k_bnparam<<<1, 64>>>(1, g2l, b2l);
        k_H<<<(NA * FF) / 256, 256>>>();
    }

    k_zero_pool<<<(BB * FF + 255) / 256, 256>>>();
    k_pool<<<NA, FF>>>(cid);
    k_head<<<BB, HH>>>(W_fc, b_fc, W_out, b_out, out);
}

// round 9
// speedup vs baseline: 1.3341x; 1.1319x over previous
#include <cuda_runtime.h>
#include <math.h>
#include <stdint.h>

// ---------------- problem dims (fixed by setup_inputs) ----------------
#define NA    100000      // atoms
#define MM    12          // neighbors per atom
#define ORIG  92          // input atom feature dim
#define NBRF  41          // neighbor (bond) feature dim
#define FF    64          // hidden feature dim
#define HH    128         // fc hidden
#define BB    2000        // crystals
#define NCONV 3
#define NM    (NA*MM)     // 1.2M edge rows
#define TWOF  (2*FF)      // 128
#define WF_ROWS (2*FF + NBRF)         // 169
#define WF_STRIDE (WF_ROWS * TWOF)    // 169*128 per layer

#define TILE_E  64                    // edges per GEMM tile
#define NTILES  (NM / TILE_E)         // 18750 exactly
#define KPAD    48                    // K padded to mult of 8
#define KSTEPS  6
#define NFS     49                    // padded k-stride for A staging
#define CSS     132                   // padded col-stride for C staging (mult of 4)
#define NATILE  7                     // max atoms spanned by a 64-edge tile
#define KG_GRID 592                   // 148 SMs * 4

// ---------------- scratch (device globals; no allocation) -------------
__device__ float  g_h[NA * FF];                 // 25.6 MB
__device__ float  g_A[NA * TWOF];               // 51.2 MB  h @ Wf_self
__device__ float  g_P[NA * TWOF];               // 51.2 MB  h @ Wf_nbr
__device__ float  g_summed[NA * FF];            // 25.6 MB (atomic-accumulated)
__device__ double g_stat1[2 * TWOF];            // sum / sumsq (128 cols)
__device__ double g_stat2[2 * FF];              // sum / sumsq (64 cols)
__device__ __align__(16) float g_bn1[2 * TWOF]; // scale(128), shift(128)
__device__ float  g_bn2[2 * FF];                // scale(64), shift(64)
__device__ float  g_pool[BB * FF];
__device__ float  g_cnt[BB];

// ---------------- helpers ----------------
__device__ __forceinline__ float softplusf_(float x) {
    // stable: max(x,0) + log(1+exp(-|x|)); __logf ok: arg in (1,2]
    return fmaxf(x, 0.f) + __logf(1.f + __expf(-fabsf(x)));
}
__device__ __forceinline__ float sigmoidf_(float x) {
    return 1.f / (1.f + __expf(-x));
}
__device__ __forceinline__ uint32_t f2tf32(float x) {
    uint32_t r;
    asm("cvt.rna.tf32.f32 %0, %1;" : "=r"(r) : "f"(x));
    return r;
}
#define MMA_TF32(c0,c1,c2,c3,a0,a1,a2,a3,b0,b1) \
    asm volatile("mma.sync.aligned.m16n8k8.row.col.f32.tf32.tf32.f32 " \
        "{%0,%1,%2,%3},{%4,%5,%6,%7},{%8,%9},{%0,%1,%2,%3};" \
        : "+f"(c0), "+f"(c1), "+f"(c2), "+f"(c3) \
        : "r"(a0), "r"(a1), "r"(a2), "r"(a3), "r"(b0), "r"(b1))

struct TileCtx {
    int tid, lane, warp, m0, r, cq;
};

__device__ __forceinline__ void pack_B(uint2* Wp, const float* __restrict__ Wf, int tid) {
    for (int i = tid; i < KSTEPS * 16 * 32; i += 128) {
        int ks = i >> 9;
        int rem = i & 511;
        int nt = rem >> 5;
        int ln = rem & 31;
        int col = nt * 8 + (ln >> 2);
        int k0 = ks * 8 + (ln & 3);
        float w0 = (k0     < NBRF) ? __ldg(&Wf[(TWOF + k0    ) * TWOF + col]) : 0.f;
        float w1 = (k0 + 4 < NBRF) ? __ldg(&Wf[(TWOF + k0 + 4) * TWOF + col]) : 0.f;
        Wp[i] = make_uint2(f2tf32(w0), f2tf32(w1));
    }
}

__device__ __forceinline__ void stage_NF(uint32_t* U, const float* __restrict__ nbr_fea,
                                         int e0, int tid) {
    for (int i = tid; i < TILE_E * NBRF; i += 128) {
        int e = i / NBRF;
        int k = i - e * NBRF;
        U[e * NFS + k] = f2tf32(nbr_fea[(size_t)e0 * NBRF + i]);
    }
    for (int i = tid; i < TILE_E * (KPAD - NBRF); i += 128) {
        int e = i / (KPAD - NBRF);
        int k = NBRF + (i - e * (KPAD - NBRF));
        U[e * NFS + k] = 0;
    }
}

// stage A rows for the tile's atoms (n_first .. n_first+6) into smem
__device__ __forceinline__ void stage_A(float* As, int n_first, int tid) {
    #pragma unroll
    for (int it = 0; it < NATILE; it++) {
        int n = n_first + it;
        if (n > NA - 1) n = NA - 1;
        As[it * TWOF + tid] = __ldg(&g_A[(size_t)n * TWOF + tid]);
    }
}

__device__ __forceinline__ void run_mma(float acc[16][4], const uint32_t* U,
                                        const uint2* Wp, const TileCtx& c) {
    #pragma unroll
    for (int nt = 0; nt < 16; nt++)
        #pragma unroll
        for (int i = 0; i < 4; i++) acc[nt][i] = 0.f;
    #pragma unroll
    for (int ks = 0; ks < KSTEPS; ks++) {
        uint32_t a0 = U[(c.m0 + c.r    ) * NFS + ks * 8 + c.cq    ];
        uint32_t a1 = U[(c.m0 + c.r + 8) * NFS + ks * 8 + c.cq    ];
        uint32_t a2 = U[(c.m0 + c.r    ) * NFS + ks * 8 + c.cq + 4];
        uint32_t a3 = U[(c.m0 + c.r + 8) * NFS + ks * 8 + c.cq + 4];
        #pragma unroll
        for (int nt = 0; nt < 16; nt++) {
            uint2 b = Wp[(ks * 16 + nt) * 32 + c.lane];
            MMA_TF32(acc[nt][0], acc[nt][1], acc[nt][2], acc[nt][3],
                     a0, a1, a2, a3, b.x, b.y);
        }
    }
}

__device__ __forceinline__ void stage_C(float* Cs, const float acc[16][4],
                                        const TileCtx& c, int h) {
    if ((c.warp >> 1) == h) {                // warps 2h, 2h+1 own these rows
        int rl = c.m0 - h * 32 + c.r;        // 0..7 or 16..23 within half
        #pragma unroll
        for (int nt = 0; nt < 16; nt++) {
            int jc = nt * 8 + 2 * c.cq;
            *(float2*)&Cs[(rl    ) * CSS + jc] = make_float2(acc[nt][0], acc[nt][1]);
            *(float2*)&Cs[(rl + 8) * CSS + jc] = make_float2(acc[nt][2], acc[nt][3]);
        }
    }
}

// ---------------- kernels ----------------

// h = atom_fea @ W_emb + b_emb    [NA,92]@[92,64]
__global__ void k_embed(const float* __restrict__ atom,
                        const float* __restrict__ W,
                        const float* __restrict__ b) {
    __shared__ float sW[ORIG * FF];
    __shared__ float sb[FF];
    __shared__ float sa[ORIG];
    int tid = threadIdx.x;            // 64 threads
    for (int i = tid; i < ORIG * FF; i += 64) sW[i] = W[i];
    if (tid < FF) sb[tid] = b[tid];
    __syncthreads();
    for (int r = 0; r < 64; r++) {
        int row = blockIdx.x * 64 + r;
        if (row >= NA) break;                    // uniform per block
        __syncthreads();
        for (int i = tid; i < ORIG; i += 64) sa[i] = atom[row * ORIG + i];
        __syncthreads();
        float acc = sb[tid];
        #pragma unroll 4
        for (int k = 0; k < ORIG; k++) acc = fmaf(sa[k], sW[k * FF + tid], acc);
        g_h[row * FF + tid] = acc;
    }
}

// A[n,j] = sum_k h[n,k] * Wf[k,j];  P[n,j] = sum_k h[n,k] * Wf[64+k,j]
__global__ void __launch_bounds__(128) k_AP(const float* __restrict__ Wf) {
    __shared__ float sh[4][FF];
    int j = threadIdx.x;              // 0..127
    int n0 = blockIdx.x * 4;
    for (int i = j; i < 4 * FF; i += 128) {
        int r = i >> 6, k = i & 63;
        sh[r][k] = g_h[(n0 + r) * FF + k];   // NA divisible by 4
    }
    __syncthreads();
    float a0 = 0, a1 = 0, a2 = 0, a3 = 0;
    float p0 = 0, p1 = 0, p2 = 0, p3 = 0;
    #pragma unroll
    for (int k = 0; k < FF; k++) {
        float wa = __ldg(&Wf[k * TWOF + j]);
        float wb = __ldg(&Wf[(FF + k) * TWOF + j]);
        a0 = fmaf(sh[0][k], wa, a0); p0 = fmaf(sh[0][k], wb, p0);
        a1 = fmaf(sh[1][k], wa, a1); p1 = fmaf(sh[1][k], wb, p1);
        a2 = fmaf(sh[2][k], wa, a2); p2 = fmaf(sh[2][k], wb, p2);
        a3 = fmaf(sh[3][k], wa, a3); p3 = fmaf(sh[3][k], wb, p3);
    }
    g_A[(n0 + 0) * TWOF + j] = a0;  g_P[(n0 + 0) * TWOF + j] = p0;
    g_A[(n0 + 1) * TWOF + j] = a1;  g_P[(n0 + 1) * TWOF + j] = p1;
    g_A[(n0 + 2) * TWOF + j] = a2;  g_P[(n0 + 2) * TWOF + j] = p2;
    g_A[(n0 + 3) * TWOF + j] = a3;  g_P[(n0 + 3) * TWOF + j] = p3;
}

// zero stats + summed accumulator
__global__ void k_zero() {
    int i = blockIdx.x * 256 + threadIdx.x;
    if (i < NA * FF) g_summed[i] = 0.f;
    if (i < 2 * TWOF) g_stat1[i] = 0.0;
    if (i < 2 * FF)   g_stat2[i] = 0.0;
}

// ---------------------------------------------------------------------
// Pass 1: k_Gstat — tf32 GEMM + A(smem)/P(float4) gather + bias -> stats.
// Epilogue threads: jq = tid&31 (col quad), g = tid>>5 (8-edge subgroup).
// ---------------------------------------------------------------------
__global__ void __launch_bounds__(128, 4) k_Gstat(const float* __restrict__ nbr_fea,
                                                  const int*   __restrict__ idx,
                                                  const float* __restrict__ Wf,
                                                  const float* __restrict__ bf) {
    __shared__ uint2 Wp[KSTEPS * 16 * 32];            // 24.0 KB
    __shared__ __align__(16) float Cs[32 * CSS];      // 16.9 KB; aliased by U
    __shared__ __align__(16) float As[NATILE * TWOF]; // 3.5 KB
    __shared__ int sidx[TILE_E];
    uint32_t* U = (uint32_t*)Cs;                      // 3136 <= 32*CSS = 4224

    TileCtx c;
    c.tid = threadIdx.x; c.lane = c.tid & 31; c.warp = c.tid >> 5;
    c.m0 = c.warp * 16; c.r = c.lane >> 2; c.cq = c.lane & 3;
    int tid = c.tid;

    pack_B(Wp, Wf, tid);

    int jq = tid & 31;           // column quad: cols 4jq..4jq+3
    int g  = tid >> 5;           // edge subgroup (8 edges) within 32-half
    float4 bf4 = __ldg((const float4*)&bf[4 * jq]);

    double ds0 = 0, ds1 = 0, ds2 = 0, ds3 = 0;
    double dq0 = 0, dq1 = 0, dq2 = 0, dq3 = 0;

    for (int t = blockIdx.x; t < NTILES; t += gridDim.x) {
        int e0 = t * TILE_E;
        int n_first = e0 / MM;
        __syncthreads();
        stage_NF(U, nbr_fea, e0, tid);
        stage_A(As, n_first, tid);
        if (tid < TILE_E) sidx[tid] = idx[e0 + tid];
        __syncthreads();

        float acc[16][4];
        run_mma(acc, U, Wp, c);
        __syncthreads();

        #pragma unroll
        for (int h = 0; h < 2; h++) {
            stage_C(Cs, acc, c, h);
            __syncthreads();
            int eg = e0 + h * 32 + g * 8;
            int n  = eg / MM;
            int rem = eg - n * MM;
            int nl  = n - n_first;
            float ts0 = 0, ts1 = 0, ts2 = 0, ts3 = 0;
            float tq0 = 0, tq1 = 0, tq2 = 0, tq3 = 0;
            #pragma unroll
            for (int i = 0; i < 8; i++) {
                int le = g * 8 + i;
                int nb = sidx[h * 32 + le];
                float4 P = __ldg((const float4*)&g_P[(size_t)nb * TWOF + 4 * jq]);
                float4 A = *(const float4*)&As[nl * TWOF + 4 * jq];
                float4 C = *(const float4*)&Cs[le * CSS + 4 * jq];
                float v0 = C.x + A.x + P.x + bf4.x;
                float v1 = C.y + A.y + P.y + bf4.y;
                float v2 = C.z + A.z + P.z + bf4.z;
                float v3 = C.w + A.w + P.w + bf4.w;
                ts0 += v0; tq0 = fmaf(v0, v0, tq0);
                ts1 += v1; tq1 = fmaf(v1, v1, tq1);
                ts2 += v2; tq2 = fmaf(v2, v2, tq2);
                ts3 += v3; tq3 = fmaf(v3, v3, tq3);
                if (++rem == MM) { rem = 0; nl++; }
            }
            ds0 += (double)ts0; ds1 += (double)ts1;
            ds2 += (double)ts2; ds3 += (double)ts3;
            dq0 += (double)tq0; dq1 += (double)tq1;
            dq2 += (double)tq2; dq3 += (double)tq3;
            __syncthreads();
        }
    }

    atomicAdd(&g_stat1[4 * jq + 0], ds0);
    atomicAdd(&g_stat1[4 * jq + 1], ds1);
    atomicAdd(&g_stat1[4 * jq + 2], ds2);
    atomicAdd(&g_stat1[4 * jq + 3], ds3);
    atomicAdd(&g_stat1[TWOF + 4 * jq + 0], dq0);
    atomicAdd(&g_stat1[TWOF + 4 * jq + 1], dq1);
    atomicAdd(&g_stat1[TWOF + 4 * jq + 2], dq2);
    atomicAdd(&g_stat1[TWOF + 4 * jq + 3], dq3);
}

// ---------------------------------------------------------------------
// Pass 2: k_GS — recompute GEMM, bn1 + sigmoid*softplus, segment-reduce
// into g_summed. Epilogue threads: jq = tid&15 (filter col quad, cols
// 4jq / 4jq+64), g = tid>>4 (4-edge subgroup). Bias folded into BN shift.
// ---------------------------------------------------------------------
__global__ void __launch_bounds__(128, 4) k_GS(const float* __restrict__ nbr_fea,
                                               const int*   __restrict__ idx,
                                               const float* __restrict__ Wf,
                                               const float* __restrict__ bf) {
    __shared__ uint2 Wp[KSTEPS * 16 * 32];
    __shared__ __align__(16) float Cs[32 * CSS];
    __shared__ __align__(16) float As[NATILE * TWOF];
    __shared__ int sidx[TILE_E];
    uint32_t* U = (uint32_t*)Cs;

    TileCtx c;
    c.tid = threadIdx.x; c.lane = c.tid & 31; c.warp = c.tid >> 5;
    c.m0 = c.warp * 16; c.r = c.lane >> 2; c.cq = c.lane & 3;
    int tid = c.tid;

    pack_B(Wp, Wf, tid);

    int jq = tid & 15;           // filter col quad: cols 4jq..4jq+3 (core +64)
    int g  = tid >> 4;           // 0..7 -> edges 4g..4g+3 of the 32-half
    float4 scf = *(const float4*)&g_bn1[4 * jq];
    float4 scc = *(const float4*)&g_bn1[FF + 4 * jq];
    float4 shf = *(const float4*)&g_bn1[TWOF + 4 * jq];
    float4 shc = *(const float4*)&g_bn1[TWOF + FF + 4 * jq];
    {
        float4 bff = __ldg((const float4*)&bf[4 * jq]);
        float4 bfc = __ldg((const float4*)&bf[FF + 4 * jq]);
        shf.x += scf.x * bff.x; shf.y += scf.y * bff.y;
        shf.z += scf.z * bff.z; shf.w += scf.w * bff.w;
        shc.x += scc.x * bfc.x; shc.y += scc.y * bfc.y;
        shc.z += scc.z * bfc.z; shc.w += scc.w * bfc.w;
    }

    for (int t = blockIdx.x; t < NTILES; t += gridDim.x) {
        int e0 = t * TILE_E;
        int n_first = e0 / MM;
        __syncthreads();
        stage_NF(U, nbr_fea, e0, tid);
        stage_A(As, n_first, tid);
        if (tid < TILE_E) sidx[tid] = idx[e0 + tid];
        __syncthreads();

        float acc[16][4];
        run_mma(acc, U, Wp, c);
        __syncthreads();

        #pragma unroll
        for (int h = 0; h < 2; h++) {
            stage_C(Cs, acc, c, h);
            __syncthreads();
            int eg = e0 + h * 32 + g * 4;
            int n  = eg / MM;
            int rem = eg - n * MM;
            int nl  = n - n_first;
            float ac0 = 0, ac1 = 0, ac2 = 0, ac3 = 0;
            #pragma unroll
            for (int i = 0; i < 4; i++) {
                int le = g * 4 + i;
                int nb = sidx[h * 32 + le];
                float4 Pf = __ldg((const float4*)&g_P[(size_t)nb * TWOF + 4 * jq]);
                float4 Pc = __ldg((const float4*)&g_P[(size_t)nb * TWOF + FF + 4 * jq]);
                float4 Af = *(const float4*)&As[nl * TWOF + 4 * jq];
                float4 Ac = *(const float4*)&As[nl * TWOF + FF + 4 * jq];
                float4 Cf = *(const float4*)&Cs[le * CSS + 4 * jq];
                float4 Cc = *(const float4*)&Cs[le * CSS + FF + 4 * jq];
                float xf0 = fmaf(scf.x, Cf.x + Af.x + Pf.x, shf.x);
                float xf1 = fmaf(scf.y, Cf.y + Af.y + Pf.y, shf.y);
                float xf2 = fmaf(scf.z, Cf.z + Af.z + Pf.z, shf.z);
                float xf3 = fmaf(scf.w, Cf.w + Af.w + Pf.w, shf.w);
                float xc0 = fmaf(scc.x, Cc.x + Ac.x + Pc.x, shc.x);
                float xc1 = fmaf(scc.y, Cc.y + Ac.y + Pc.y, shc.y);
                float xc2 = fmaf(scc.z, Cc.z + Ac.z + Pc.z, shc.z);
                float xc3 = fmaf(scc.w, Cc.w + Ac.w + Pc.w, shc.w);
                ac0 = fmaf(sigmoidf_(xf0), softplusf_(xc0), ac0);
                ac1 = fmaf(sigmoidf_(xf1), softplusf_(xc1), ac1);
                ac2 = fmaf(sigmoidf_(xf2), softplusf_(xc2), ac2);
                ac3 = fmaf(sigmoidf_(xf3), softplusf_(xc3), ac3);
                if (++rem == MM) {
                    atomicAdd(&g_summed[n * FF + 4 * jq + 0], ac0);
                    atomicAdd(&g_summed[n * FF + 4 * jq + 1], ac1);
                    atomicAdd(&g_summed[n * FF + 4 * jq + 2], ac2);
                    atomicAdd(&g_summed[n * FF + 4 * jq + 3], ac3);
                    ac0 = ac1 = ac2 = ac3 = 0.f;
                    rem = 0; n++; nl++;
                }
            }
            if (rem != 0) {
                atomicAdd(&g_summed[n * FF + 4 * jq + 0], ac0);
                atomicAdd(&g_summed[n * FF + 4 * jq + 1], ac1);
                atomicAdd(&g_summed[n * FF + 4 * jq + 2], ac2);
                atomicAdd(&g_summed[n * FF + 4 * jq + 3], ac3);
            }
            __syncthreads();
        }
    }
}

// stats over g_summed (per column over atoms)
__global__ void __launch_bounds__(256) k_stat2() {
    int tid = threadIdx.x;
    int j = tid & 63;
    int grp = tid >> 6;                       // 0..3
    float s = 0.f, s2 = 0.f;
    int nBase = blockIdx.x * 256 + grp * 64;
    for (int t = 0; t < 64; t++) {
        int n = nBase + t;
        if (n >= NA) break;                   // uniform within group
        float v = g_summed[n * FF + j];
        s += v;
        s2 = fmaf(v, v, s2);
    }
    atomicAdd(&g_stat2[j], (double)s);
    atomicAdd(&g_stat2[FF + j], (double)s2);
}

// BN affine params from accumulated stats.
__global__ void k_bnparam(int which,
                          const float* __restrict__ gamma,
                          const float* __restrict__ beta) {
    int j = threadIdx.x;
    if (which == 0) {
        if (j >= TWOF) return;
        double inv = 1.0 / (double)NM;
        double mu = g_stat1[j] * inv;
        double var = g_stat1[TWOF + j] * inv - mu * mu;
        float sc = gamma[j] * rsqrtf((float)var + 1e-5f);
        g_bn1[j] = sc;
        g_bn1[TWOF + j] = beta[j] - (float)mu * sc;
    } else {
        if (j >= FF) return;
        double inv = 1.0 / (double)NA;
        double mu = g_stat2[j] * inv;
        double var = g_stat2[FF + j] * inv - mu * mu;
        float sc = gamma[j] * rsqrtf((float)var + 1e-5f);
        g_bn2[j] = sc;
        g_bn2[FF + j] = beta[j] - (float)mu * sc;
    }
}

// h = softplus(h + bn2(summed))
__global__ void k_H() {
    int i = blockIdx.x * blockDim.x + threadIdx.x;
    if (i >= NA * FF) return;
    int j = i & 63;
    float x = fmaf(g_bn2[j], g_summed[i], g_bn2[FF + j]);
    g_h[i] = softplusf_(g_h[i] + x);
}

__global__ void k_zero_pool() {
    int i = blockIdx.x * 256 + threadIdx.x;
    if (i < BB * FF) g_pool[i] = 0.f;
    if (i < BB) g_cnt[i] = 0.f;
}

__global__ void k_pool(const int* __restrict__ cid) {
    int n = blockIdx.x;
    int c = cid[n];
    atomicAdd(&g_pool[c * FF + threadIdx.x], g_h[n * FF + threadIdx.x]);
    if (threadIdx.x == 0) atomicAdd(&g_cnt[c], 1.f);
}

// crys = pool/cnt; out[b] = softplus(crys@W_fc + b_fc) @ W_out + b_out
__global__ void k_head(const float* __restrict__ Wfc,
                       const float* __restrict__ bfc,
                       const float* __restrict__ Wout,
                       const float* __restrict__ bout,
                       float* __restrict__ out) {
    int b = blockIdx.x;
    int t = threadIdx.x;                      // 128
    __shared__ float sc[FF];
    __shared__ float red[HH];
    float inv = 1.f / fmaxf(g_cnt[b], 1.f);
    if (t < FF) sc[t] = g_pool[b * FF + t] * inv;
    __syncthreads();
    float acc = bfc[t];
    #pragma unroll
    for (int k = 0; k < FF; k++) acc = fmaf(sc[k], __ldg(&Wfc[k * HH + t]), acc);
    red[t] = softplusf_(acc) * __ldg(&Wout[t]);
    __syncthreads();
    for (int off = 64; off > 0; off >>= 1) {
        if (t < off) red[t] += red[t + off];
        __syncthreads();
    }
    if (t == 0) out[b] = red[0] + bout[0];
}

// ---------------- launch ----------------
extern "C" void kernel_launch(void* const* d_in, const int* in_sizes, int n_in,
                              void* d_out, int out_size) {
    const float* atom_fea = (const float*)d_in[0];
    const float* nbr_fea  = (const float*)d_in[1];
    const int*   nbr_idx  = (const int*)d_in[2];
    const int*   cid      = (const int*)d_in[3];
    int o = (n_in >= 17 && in_sizes[4] == 1) ? 1 : 0;
    const float* W_emb = (const float*)d_in[4 + o];
    const float* b_emb = (const float*)d_in[5 + o];
    const float* Wf    = (const float*)d_in[6 + o];
    const float* bf    = (const float*)d_in[7 + o];
    const float* g1    = (const float*)d_in[8 + o];
    const float* b1    = (const float*)d_in[9 + o];
    const float* g2    = (const float*)d_in[10 + o];
    const float* b2    = (const float*)d_in[11 + o];
    const float* W_fc  = (const float*)d_in[12 + o];
    const float* b_fc  = (const float*)d_in[13 + o];
    const float* W_out = (const float*)d_in[14 + o];
    const float* b_out = (const float*)d_in[15 + o];
    float* out = (float*)d_out;

    k_embed<<<(NA + 63) / 64, 64>>>(atom_fea, W_emb, b_emb);

    for (int l = 0; l < NCONV; l++) {
        const float* Wfl = Wf + l * WF_STRIDE;
        const float* bfl = bf + l * TWOF;
        const float* g1l = g1 + l * TWOF;
        const float* b1l = b1 + l * TWOF;
        const float* g2l = g2 + l * FF;
        const float* b2l = b2 + l * FF;

        k_zero<<<(NA * FF + 255) / 256, 256>>>();
        k_AP<<<NA / 4, 128>>>(Wfl);
        k_Gstat<<<KG_GRID, 128>>>(nbr_fea, nbr_idx, Wfl, bfl);
        k_bnparam<<<1, 128>>>(0, g1l, b1l);
        k_GS<<<KG_GRID, 128>>>(nbr_fea, nbr_idx, Wfl, bfl);
        k_stat2<<<(NA + 255) / 256, 256>>>();
        k_bnparam<<<1, 64>>>(1, g2l, b2l);
        k_H<<<(NA * FF) / 256, 256>>>();
    }

    k_zero_pool<<<(BB * FF + 255) / 256, 256>>>();
    k_pool<<<NA, FF>>>(cid);
    k_head<<<BB, HH>>>(W_fc, b_fc, W_out, b_out, out);
}

// round 10
// speedup vs baseline: 1.6783x; 1.2580x over previous
#include <cuda_runtime.h>
#include <cuda_fp16.h>
#include <math.h>
#include <stdint.h>

// ---------------- problem dims (fixed by setup_inputs) ----------------
#define NA    100000      // atoms
#define MM    12          // neighbors per atom
#define ORIG  92          // input atom feature dim
#define NBRF  41          // neighbor (bond) feature dim
#define FF    64          // hidden feature dim
#define HH    128         // fc hidden
#define BB    2000        // crystals
#define NCONV 3
#define NM    (NA*MM)     // 1.2M edge rows
#define TWOF  (2*FF)      // 128
#define WF_ROWS (2*FF + NBRF)         // 169
#define WF_STRIDE (WF_ROWS * TWOF)    // 169*128 per layer

#define TILE_E  64                    // edges per GEMM tile
#define NTILES  (NM / TILE_E)         // 18750 exactly
#define KPAD    48                    // K padded to mult of 8
#define KSTEPS  6
#define NFS     49                    // padded k-stride for A staging
#define CSS     132                   // padded col-stride for C staging (mult of 4)
#define NATILE  7                     // max atoms spanned by a 64-edge tile
#define KG_GRID 740                   // 148 SMs * 5

// ---------------- scratch (device globals; no allocation) -------------
__device__ float  g_h[NA * FF];                 // 25.6 MB
__device__ float  g_A[NA * TWOF];               // 51.2 MB  h @ Wf_self
__device__ float  g_P[NA * TWOF];               // 51.2 MB  h @ Wf_nbr
__device__ __half g_Gh[NM * TWOF];              // 307 MB   fp16 gated pre-BN
__device__ __align__(16) float g_summed[NA * FF];  // 25.6 MB
__device__ double g_stat1[2 * TWOF];            // sum / sumsq (128 cols)
__device__ double g_stat2[2 * FF];              // sum / sumsq (64 cols)
__device__ __align__(16) float g_bn1[2 * TWOF]; // scale(128), shift(128)
__device__ float  g_bn2[2 * FF];                // scale(64), shift(64)
__device__ float  g_pool[BB * FF];
__device__ float  g_cnt[BB];

// ---------------- helpers ----------------
__device__ __forceinline__ float softplusf_(float x) {
    return fmaxf(x, 0.f) + __logf(1.f + __expf(-fabsf(x)));
}
__device__ __forceinline__ float sigmoidf_(float x) {
    return 1.f / (1.f + __expf(-x));
}
__device__ __forceinline__ uint32_t f2tf32(float x) {
    uint32_t r;
    asm("cvt.rna.tf32.f32 %0, %1;" : "=r"(r) : "f"(x));
    return r;
}
#define MMA_TF32(c0,c1,c2,c3,a0,a1,a2,a3,b0,b1) \
    asm volatile("mma.sync.aligned.m16n8k8.row.col.f32.tf32.tf32.f32 " \
        "{%0,%1,%2,%3},{%4,%5,%6,%7},{%8,%9},{%0,%1,%2,%3};" \
        : "+f"(c0), "+f"(c1), "+f"(c2), "+f"(c3) \
        : "r"(a0), "r"(a1), "r"(a2), "r"(a3), "r"(b0), "r"(b1))

struct TileCtx {
    int tid, lane, warp, m0, r, cq;
};

__device__ __forceinline__ void pack_B(uint2* Wp, const float* __restrict__ Wf, int tid) {
    for (int i = tid; i < KSTEPS * 16 * 32; i += 128) {
        int ks = i >> 9;
        int rem = i & 511;
        int nt = rem >> 5;
        int ln = rem & 31;
        int col = nt * 8 + (ln >> 2);
        int k0 = ks * 8 + (ln & 3);
        float w0 = (k0     < NBRF) ? __ldg(&Wf[(TWOF + k0    ) * TWOF + col]) : 0.f;
        float w1 = (k0 + 4 < NBRF) ? __ldg(&Wf[(TWOF + k0 + 4) * TWOF + col]) : 0.f;
        Wp[i] = make_uint2(f2tf32(w0), f2tf32(w1));
    }
}

__device__ __forceinline__ void stage_NF(uint32_t* U, const float* __restrict__ nbr_fea,
                                         int e0, int tid) {
    for (int i = tid; i < TILE_E * NBRF; i += 128) {
        int e = i / NBRF;
        int k = i - e * NBRF;
        U[e * NFS + k] = f2tf32(nbr_fea[(size_t)e0 * NBRF + i]);
    }
    for (int i = tid; i < TILE_E * (KPAD - NBRF); i += 128) {
        int e = i / (KPAD - NBRF);
        int k = NBRF + (i - e * (KPAD - NBRF));
        U[e * NFS + k] = 0;
    }
}

// stage A rows for the tile's atoms into smem
__device__ __forceinline__ void stage_A(float* As, int n_first, int tid) {
    #pragma unroll
    for (int it = 0; it < NATILE; it++) {
        int n = n_first + it;
        if (n > NA - 1) n = NA - 1;
        As[it * TWOF + tid] = __ldg(&g_A[(size_t)n * TWOF + tid]);
    }
}

__device__ __forceinline__ void run_mma(float acc[16][4], const uint32_t* U,
                                        const uint2* Wp, const TileCtx& c) {
    #pragma unroll
    for (int nt = 0; nt < 16; nt++)
        #pragma unroll
        for (int i = 0; i < 4; i++) acc[nt][i] = 0.f;
    #pragma unroll
    for (int ks = 0; ks < KSTEPS; ks++) {
        uint32_t a0 = U[(c.m0 + c.r    ) * NFS + ks * 8 + c.cq    ];
        uint32_t a1 = U[(c.m0 + c.r + 8) * NFS + ks * 8 + c.cq    ];
        uint32_t a2 = U[(c.m0 + c.r    ) * NFS + ks * 8 + c.cq + 4];
        uint32_t a3 = U[(c.m0 + c.r + 8) * NFS + ks * 8 + c.cq + 4];
        #pragma unroll
        for (int nt = 0; nt < 16; nt++) {
            uint2 b = Wp[(ks * 16 + nt) * 32 + c.lane];
            MMA_TF32(acc[nt][0], acc[nt][1], acc[nt][2], acc[nt][3],
                     a0, a1, a2, a3, b.x, b.y);
        }
    }
}

__device__ __forceinline__ void stage_C(float* Cs, const float acc[16][4],
                                        const TileCtx& c, int h) {
    if ((c.warp >> 1) == h) {
        int rl = c.m0 - h * 32 + c.r;
        #pragma unroll
        for (int nt = 0; nt < 16; nt++) {
            int jc = nt * 8 + 2 * c.cq;
            *(float2*)&Cs[(rl    ) * CSS + jc] = make_float2(acc[nt][0], acc[nt][1]);
            *(float2*)&Cs[(rl + 8) * CSS + jc] = make_float2(acc[nt][2], acc[nt][3]);
        }
    }
}

// ---------------- kernels ----------------

// h = atom_fea @ W_emb + b_emb    [NA,92]@[92,64]
__global__ void k_embed(const float* __restrict__ atom,
                        const float* __restrict__ W,
                        const float* __restrict__ b) {
    __shared__ float sW[ORIG * FF];
    __shared__ float sb[FF];
    __shared__ float sa[ORIG];
    int tid = threadIdx.x;            // 64 threads
    for (int i = tid; i < ORIG * FF; i += 64) sW[i] = W[i];
    if (tid < FF) sb[tid] = b[tid];
    __syncthreads();
    for (int r = 0; r < 64; r++) {
        int row = blockIdx.x * 64 + r;
        if (row >= NA) break;
        __syncthreads();
        for (int i = tid; i < ORIG; i += 64) sa[i] = atom[row * ORIG + i];
        __syncthreads();
        float acc = sb[tid];
        #pragma unroll 4
        for (int k = 0; k < ORIG; k++) acc = fmaf(sa[k], sW[k * FF + tid], acc);
        g_h[row * FF + tid] = acc;
    }
}

// A[n,j] = sum_k h[n,k] * Wf[k,j];  P[n,j] = sum_k h[n,k] * Wf[64+k,j]
__global__ void __launch_bounds__(128) k_AP(const float* __restrict__ Wf) {
    __shared__ float sh[4][FF];
    int j = threadIdx.x;
    int n0 = blockIdx.x * 4;
    for (int i = j; i < 4 * FF; i += 128) {
        int r = i >> 6, k = i & 63;
        sh[r][k] = g_h[(n0 + r) * FF + k];
    }
    __syncthreads();
    float a0 = 0, a1 = 0, a2 = 0, a3 = 0;
    float p0 = 0, p1 = 0, p2 = 0, p3 = 0;
    #pragma unroll
    for (int k = 0; k < FF; k++) {
        float wa = __ldg(&Wf[k * TWOF + j]);
        float wb = __ldg(&Wf[(FF + k) * TWOF + j]);
        a0 = fmaf(sh[0][k], wa, a0); p0 = fmaf(sh[0][k], wb, p0);
        a1 = fmaf(sh[1][k], wa, a1); p1 = fmaf(sh[1][k], wb, p1);
        a2 = fmaf(sh[2][k], wa, a2); p2 = fmaf(sh[2][k], wb, p2);
        a3 = fmaf(sh[3][k], wa, a3); p3 = fmaf(sh[3][k], wb, p3);
    }
    g_A[(n0 + 0) * TWOF + j] = a0;  g_P[(n0 + 0) * TWOF + j] = p0;
    g_A[(n0 + 1) * TWOF + j] = a1;  g_P[(n0 + 1) * TWOF + j] = p1;
    g_A[(n0 + 2) * TWOF + j] = a2;  g_P[(n0 + 2) * TWOF + j] = p2;
    g_A[(n0 + 3) * TWOF + j] = a3;  g_P[(n0 + 3) * TWOF + j] = p3;
}

// zero the stat accumulators only (g_summed is overwritten by k_S2)
__global__ void k_zero() {
    int i = threadIdx.x;
    if (i < 2 * TWOF) g_stat1[i] = 0.0;
    if (i < 2 * FF)   g_stat2[i] = 0.0;
}

// ---------------------------------------------------------------------
// Pass 1: k_G1 — tf32 GEMM + A(smem)/P(float4) gather + bias ->
// column stats (fp32 accum -> fp64 atomic) + fp16 spill of G.
// Epilogue threads: jq = tid&31 (col quad), g = tid>>5 (8-edge subgroup).
// ---------------------------------------------------------------------
__global__ void __launch_bounds__(128, 5) k_G1(const float* __restrict__ nbr_fea,
                                               const int*   __restrict__ idx,
                                               const float* __restrict__ Wf,
                                               const float* __restrict__ bf) {
    __shared__ uint2 Wp[KSTEPS * 16 * 32];            // 24.0 KB
    __shared__ __align__(16) float Cs[32 * CSS];      // 16.9 KB; aliased by U
    __shared__ __align__(16) float As[NATILE * TWOF]; // 3.5 KB
    __shared__ int sidx[TILE_E];
    uint32_t* U = (uint32_t*)Cs;                      // 3136 <= 32*CSS = 4224

    TileCtx c;
    c.tid = threadIdx.x; c.lane = c.tid & 31; c.warp = c.tid >> 5;
    c.m0 = c.warp * 16; c.r = c.lane >> 2; c.cq = c.lane & 3;
    int tid = c.tid;

    pack_B(Wp, Wf, tid);

    int jq = tid & 31;           // column quad: cols 4jq..4jq+3
    int g  = tid >> 5;           // edge subgroup (8 edges) within 32-half
    float4 bf4 = __ldg((const float4*)&bf[4 * jq]);

    float ds0 = 0, ds1 = 0, ds2 = 0, ds3 = 0;
    float dq0 = 0, dq1 = 0, dq2 = 0, dq3 = 0;

    for (int t = blockIdx.x; t < NTILES; t += gridDim.x) {
        int e0 = t * TILE_E;
        int n_first = e0 / MM;
        __syncthreads();
        stage_NF(U, nbr_fea, e0, tid);
        stage_A(As, n_first, tid);
        if (tid < TILE_E) sidx[tid] = idx[e0 + tid];
        __syncthreads();

        float acc[16][4];
        run_mma(acc, U, Wp, c);
        __syncthreads();

        #pragma unroll
        for (int h = 0; h < 2; h++) {
            stage_C(Cs, acc, c, h);
            __syncthreads();
            int eg = e0 + h * 32 + g * 8;
            int n  = eg / MM;
            int rem = eg - n * MM;
            int nl  = n - n_first;
            float ts0 = 0, ts1 = 0, ts2 = 0, ts3 = 0;
            float tq0 = 0, tq1 = 0, tq2 = 0, tq3 = 0;
            #pragma unroll
            for (int i = 0; i < 8; i++) {
                int le = g * 8 + i;
                int nb = sidx[h * 32 + le];
                float4 P = __ldg((const float4*)&g_P[(size_t)nb * TWOF + 4 * jq]);
                float4 A = *(const float4*)&As[nl * TWOF + 4 * jq];
                float4 C = *(const float4*)&Cs[le * CSS + 4 * jq];
                float v0 = C.x + A.x + P.x + bf4.x;
                float v1 = C.y + A.y + P.y + bf4.y;
                float v2 = C.z + A.z + P.z + bf4.z;
                float v3 = C.w + A.w + P.w + bf4.w;
                ts0 += v0; tq0 = fmaf(v0, v0, tq0);
                ts1 += v1; tq1 = fmaf(v1, v1, tq1);
                ts2 += v2; tq2 = fmaf(v2, v2, tq2);
                ts3 += v3; tq3 = fmaf(v3, v3, tq3);
                // fp16 spill (includes bias)
                {
                    __half2 ha = __floats2half2_rn(v0, v1);
                    __half2 hb = __floats2half2_rn(v2, v3);
                    uint2 u;
                    u.x = *reinterpret_cast<unsigned*>(&ha);
                    u.y = *reinterpret_cast<unsigned*>(&hb);
                    *reinterpret_cast<uint2*>(&g_Gh[(size_t)(eg + i) * TWOF + 4 * jq]) = u;
                }
                if (++rem == MM) { rem = 0; nl++; }
            }
            ds0 += ts0; ds1 += ts1; ds2 += ts2; ds3 += ts3;
            dq0 += tq0; dq1 += tq1; dq2 += tq2; dq3 += tq3;
            __syncthreads();
        }
    }

    atomicAdd(&g_stat1[4 * jq + 0], (double)ds0);
    atomicAdd(&g_stat1[4 * jq + 1], (double)ds1);
    atomicAdd(&g_stat1[4 * jq + 2], (double)ds2);
    atomicAdd(&g_stat1[4 * jq + 3], (double)ds3);
    atomicAdd(&g_stat1[TWOF + 4 * jq + 0], (double)dq0);
    atomicAdd(&g_stat1[TWOF + 4 * jq + 1], (double)dq1);
    atomicAdd(&g_stat1[TWOF + 4 * jq + 2], (double)dq2);
    atomicAdd(&g_stat1[TWOF + 4 * jq + 3], (double)dq3);
}

// ---------------------------------------------------------------------
// Pass 2: k_S2 — stream fp16 G, bn1 + sigmoid*softplus, per-atom reduce,
// DIRECT store to g_summed (no atomics). 256 thr = 16 atoms x 16 col-quads.
// ---------------------------------------------------------------------
__global__ void __launch_bounds__(256) k_S2() {
    int tid = threadIdx.x;
    int t = tid & 15;                 // filter col quad: cols 4t..4t+3
    int a = tid >> 4;                 // atom within block (0..15)
    int n = blockIdx.x * 16 + a;      // grid = NA/16 = 6250 exact

    float4 scf = *(const float4*)&g_bn1[4 * t];
    float4 scc = *(const float4*)&g_bn1[FF + 4 * t];
    float4 shf = *(const float4*)&g_bn1[TWOF + 4 * t];
    float4 shc = *(const float4*)&g_bn1[TWOF + FF + 4 * t];

    size_t base = (size_t)n * MM * TWOF;
    float s0 = 0, s1 = 0, s2 = 0, s3 = 0;
    #pragma unroll
    for (int m = 0; m < MM; m++) {
        uint2 uf = __ldg((const uint2*)&g_Gh[base + m * TWOF + 4 * t]);
        uint2 uc = __ldg((const uint2*)&g_Gh[base + m * TWOF + FF + 4 * t]);
        float2 f01 = __half22float2(*reinterpret_cast<__half2*>(&uf.x));
        float2 f23 = __half22float2(*reinterpret_cast<__half2*>(&uf.y));
        float2 c01 = __half22float2(*reinterpret_cast<__half2*>(&uc.x));
        float2 c23 = __half22float2(*reinterpret_cast<__half2*>(&uc.y));
        float xf0 = fmaf(scf.x, f01.x, shf.x);
        float xf1 = fmaf(scf.y, f01.y, shf.y);
        float xf2 = fmaf(scf.z, f23.x, shf.z);
        float xf3 = fmaf(scf.w, f23.y, shf.w);
        float xc0 = fmaf(scc.x, c01.x, shc.x);
        float xc1 = fmaf(scc.y, c01.y, shc.y);
        float xc2 = fmaf(scc.z, c23.x, shc.z);
        float xc3 = fmaf(scc.w, c23.y, shc.w);
        s0 = fmaf(sigmoidf_(xf0), softplusf_(xc0), s0);
        s1 = fmaf(sigmoidf_(xf1), softplusf_(xc1), s1);
        s2 = fmaf(sigmoidf_(xf2), softplusf_(xc2), s2);
        s3 = fmaf(sigmoidf_(xf3), softplusf_(xc3), s3);
    }
    *(float4*)&g_summed[n * FF + 4 * t] = make_float4(s0, s1, s2, s3);
}

// stats over g_summed (per column over atoms)
__global__ void __launch_bounds__(256) k_stat2() {
    int tid = threadIdx.x;
    int j = tid & 63;
    int grp = tid >> 6;
    float s = 0.f, s2 = 0.f;
    int nBase = blockIdx.x * 256 + grp * 64;
    for (int t = 0; t < 64; t++) {
        int n = nBase + t;
        if (n >= NA) break;
        float v = g_summed[n * FF + j];
        s += v;
        s2 = fmaf(v, v, s2);
    }
    atomicAdd(&g_stat2[j], (double)s);
    atomicAdd(&g_stat2[FF + j], (double)s2);
}

// BN affine params from accumulated stats.
__global__ void k_bnparam(int which,
                          const float* __restrict__ gamma,
                          const float* __restrict__ beta) {
    int j = threadIdx.x;
    if (which == 0) {
        if (j >= TWOF) return;
        double inv = 1.0 / (double)NM;
        double mu = g_stat1[j] * inv;
        double var = g_stat1[TWOF + j] * inv - mu * mu;
        float sc = gamma[j] * rsqrtf((float)var + 1e-5f);
        g_bn1[j] = sc;
        g_bn1[TWOF + j] = beta[j] - (float)mu * sc;
    } else {
        if (j >= FF) return;
        double inv = 1.0 / (double)NA;
        double mu = g_stat2[j] * inv;
        double var = g_stat2[FF + j] * inv - mu * mu;
        float sc = gamma[j] * rsqrtf((float)var + 1e-5f);
        g_bn2[j] = sc;
        g_bn2[FF + j] = beta[j] - (float)mu * sc;
    }
}

// h = softplus(h + bn2(summed))
__global__ void k_H() {
    int i = blockIdx.x * blockDim.x + threadIdx.x;
    if (i >= NA * FF) return;
    int j = i & 63;
    float x = fmaf(g_bn2[j], g_summed[i], g_bn2[FF + j]);
    g_h[i] = softplusf_(g_h[i] + x);
}

__global__ void k_zero_pool() {
    int i = blockIdx.x * 256 + threadIdx.x;
    if (i < BB * FF) g_pool[i] = 0.f;
    if (i < BB) g_cnt[i] = 0.f;
}

__global__ void k_pool(const int* __restrict__ cid) {
    int n = blockIdx.x;
    int c = cid[n];
    atomicAdd(&g_pool[c * FF + threadIdx.x], g_h[n * FF + threadIdx.x]);
    if (threadIdx.x == 0) atomicAdd(&g_cnt[c], 1.f);
}

// crys = pool/cnt; out[b] = softplus(crys@W_fc + b_fc) @ W_out + b_out
__global__ void k_head(const float* __restrict__ Wfc,
                       const float* __restrict__ bfc,
                       const float* __restrict__ Wout,
                       const float* __restrict__ bout,
                       float* __restrict__ out) {
    int b = blockIdx.x;
    int t = threadIdx.x;
    __shared__ float sc[FF];
    __shared__ float red[HH];
    float inv = 1.f / fmaxf(g_cnt[b], 1.f);
    if (t < FF) sc[t] = g_pool[b * FF + t] * inv;
    __syncthreads();
    float acc = bfc[t];
    #pragma unroll
    for (int k = 0; k < FF; k++) acc = fmaf(sc[k], __ldg(&Wfc[k * HH + t]), acc);
    red[t] = softplusf_(acc) * __ldg(&Wout[t]);
    __syncthreads();
    for (int off = 64; off > 0; off >>= 1) {
        if (t < off) red[t] += red[t + off];
        __syncthreads();
    }
    if (t == 0) out[b] = red[0] + bout[0];
}

// ---------------- launch ----------------
extern "C" void kernel_launch(void* const* d_in, const int* in_sizes, int n_in,
                              void* d_out, int out_size) {
    const float* atom_fea = (const float*)d_in[0];
    const float* nbr_fea  = (const float*)d_in[1];
    const int*   nbr_idx  = (const int*)d_in[2];
    const int*   cid      = (const int*)d_in[3];
    int o = (n_in >= 17 && in_sizes[4] == 1) ? 1 : 0;
    const float* W_emb = (const float*)d_in[4 + o];
    const float* b_emb = (const float*)d_in[5 + o];
    const float* Wf    = (const float*)d_in[6 + o];
    const float* bf    = (const float*)d_in[7 + o];
    const float* g1    = (const float*)d_in[8 + o];
    const float* b1    = (const float*)d_in[9 + o];
    const float* g2    = (const float*)d_in[10 + o];
    const float* b2    = (const float*)d_in[11 + o];
    const float* W_fc  = (const float*)d_in[12 + o];
    const float* b_fc  = (const float*)d_in[13 + o];
    const float* W_out = (const float*)d_in[14 + o];
    const float* b_out = (const float*)d_in[15 + o];
    float* out = (float*)d_out;

    k_embed<<<(NA + 63) / 64, 64>>>(atom_fea, W_emb, b_emb);

    for (int l = 0; l < NCONV; l++) {
        const float* Wfl = Wf + l * WF_STRIDE;
        const float* bfl = bf + l * TWOF;
        const float* g1l = g1 + l * TWOF;
        const float* b1l = b1 + l * TWOF;
        const float* g2l = g2 + l * FF;
        const float* b2l = b2 + l * FF;

        k_zero<<<1, 384>>>();
        k_AP<<<NA / 4, 128>>>(Wfl);
        k_G1<<<KG_GRID, 128>>>(nbr_fea, nbr_idx, Wfl, bfl);
        k_bnparam<<<1, 128>>>(0, g1l, b1l);
        k_S2<<<NA / 16, 256>>>();
        k_stat2<<<(NA + 255) / 256, 256>>>();
        k_bnparam<<<1, 64>>>(1, g2l, b2l);
        k_H<<<(NA * FF) / 256, 256>>>();
    }

    k_zero_pool<<<(BB * FF + 255) / 256, 256>>>();
    k_pool<<<NA, FF>>>(cid);
    k_head<<<BB, HH>>>(W_fc, b_fc, W_out, b_out, out);
}

// round 13
// speedup vs baseline: 1.7129x; 1.0206x over previous
#include <cuda_runtime.h>
#include <cuda_fp16.h>
#include <math.h>
#include <stdint.h>

// ---------------- problem dims (fixed by setup_inputs) ----------------
#define NA    100000      // atoms
#define MM    12          // neighbors per atom
#define ORIG  92          // input atom feature dim
#define NBRF  41          // neighbor (bond) feature dim
#define FF    64          // hidden feature dim
#define HH    128         // fc hidden
#define BB    2000        // crystals
#define NCONV 3
#define NM    (NA*MM)     // 1.2M edge rows
#define TWOF  (2*FF)      // 128
#define WF_ROWS (2*FF + NBRF)         // 169
#define WF_STRIDE (WF_ROWS * TWOF)    // 169*128 per layer

#define TILE_E  64                    // edges per GEMM tile
#define NTILES  (NM / TILE_E)         // 18750 exactly
#define KPAD    48                    // K padded to mult of 8
#define KSTEPS  6
#define NFS     49                    // padded k-stride for A staging
#define CSS     132                   // padded col-stride for C staging (mult of 4)
#define NATILE  7                     // max atoms spanned by a 64-edge tile
#define KG_GRID 740                   // 148 SMs * 5

// ---------------- scratch (device globals; no allocation) -------------
__device__ float  g_h[NA * FF];                 // 25.6 MB
__device__ float  g_A[NA * TWOF];               // 51.2 MB  h @ Wf_self
__device__ float  g_P[NA * TWOF];               // 51.2 MB  h @ Wf_nbr
__device__ __half g_Gh[NM * TWOF];              // 307 MB   fp16 gated pre-BN
__device__ __align__(16) float g_summed[NA * FF];  // 25.6 MB
__device__ double g_stat1[2 * TWOF];            // sum / sumsq (128 cols)
__device__ double g_stat2[2 * FF];              // sum / sumsq (64 cols)
__device__ __align__(16) float g_bn1[2 * TWOF]; // scale(128), shift(128)
__device__ float  g_bn2[2 * FF];                // scale(64), shift(64)
__device__ float  g_pool[BB * FF];
__device__ float  g_cnt[BB];

// ---------------- helpers ----------------
__device__ __forceinline__ float softplusf_(float x) {
    return fmaxf(x, 0.f) + __logf(1.f + __expf(-fabsf(x)));
}
__device__ __forceinline__ float sigmoidf_(float x) {
    return 1.f / (1.f + __expf(-x));
}
__device__ __forceinline__ uint32_t f2tf32(float x) {
    uint32_t r;
    asm("cvt.rna.tf32.f32 %0, %1;" : "=r"(r) : "f"(x));
    return r;
}
#define MMA_TF32(c0,c1,c2,c3,a0,a1,a2,a3,b0,b1) \
    asm volatile("mma.sync.aligned.m16n8k8.row.col.f32.tf32.tf32.f32 " \
        "{%0,%1,%2,%3},{%4,%5,%6,%7},{%8,%9},{%0,%1,%2,%3};" \
        : "+f"(c0), "+f"(c1), "+f"(c2), "+f"(c3) \
        : "r"(a0), "r"(a1), "r"(a2), "r"(a3), "r"(b0), "r"(b1))

struct TileCtx {
    int tid, lane, warp, m0, r, cq;
};

// Pack B fragments as uint4 pairs: Wp4[(ks*8 + ntp)*32 + lane] holds the
// b-frags for n-tiles 2*ntp (x,y) and 2*ntp+1 (z,w). One LDS.128 per 2 MMAs.
__device__ __forceinline__ void pack_B(uint4* Wp4, const float* __restrict__ Wf, int tid) {
    for (int i = tid; i < KSTEPS * 8 * 32; i += 128) {
        int ks  = i >> 8;            // /(8*32)
        int rem = i & 255;
        int ntp = rem >> 5;
        int ln  = rem & 31;
        int col0 = (2 * ntp) * 8 + (ln >> 2);
        int col1 = col0 + 8;
        int k0 = ks * 8 + (ln & 3);
        float w0 = (k0     < NBRF) ? __ldg(&Wf[(TWOF + k0    ) * TWOF + col0]) : 0.f;
        float w1 = (k0 + 4 < NBRF) ? __ldg(&Wf[(TWOF + k0 + 4) * TWOF + col0]) : 0.f;
        float w2 = (k0     < NBRF) ? __ldg(&Wf[(TWOF + k0    ) * TWOF + col1]) : 0.f;
        float w3 = (k0 + 4 < NBRF) ? __ldg(&Wf[(TWOF + k0 + 4) * TWOF + col1]) : 0.f;
        Wp4[i] = make_uint4(f2tf32(w0), f2tf32(w1), f2tf32(w2), f2tf32(w3));
    }
}

// Stage NF tile with float4 gmem loads (tile is contiguous: 64*41 floats,
// 16B-aligned since e0*41*4 is a multiple of 16 for e0 mult of 64).
__device__ __forceinline__ void stage_NF(uint32_t* U, const float* __restrict__ nbr_fea,
                                         int e0, int tid) {
    const int NQ = TILE_E * NBRF / 4;   // 656
    for (int i = tid; i < NQ; i += 128) {
        float4 v = __ldg((const float4*)&nbr_fea[(size_t)e0 * NBRF + 4 * i]);
        int base = 4 * i;
        int e = base / NBRF;
        int k = base - e * NBRF;
        float vv[4] = {v.x, v.y, v.z, v.w};
        #pragma unroll
        for (int u = 0; u < 4; u++) {
            U[e * NFS + k] = f2tf32(vv[u]);
            if (++k == NBRF) { k = 0; e++; }
        }
    }
    for (int i = tid; i < TILE_E * (KPAD - NBRF); i += 128) {
        int e = i / (KPAD - NBRF);
        int k = NBRF + (i - e * (KPAD - NBRF));
        U[e * NFS + k] = 0;
    }
}

// stage A rows for the tile's atoms into smem
__device__ __forceinline__ void stage_A(float* As, int n_first, int tid) {
    #pragma unroll
    for (int it = 0; it < NATILE; it++) {
        int n = n_first + it;
        if (n > NA - 1) n = NA - 1;
        As[it * TWOF + tid] = __ldg(&g_A[(size_t)n * TWOF + tid]);
    }
}

__device__ __forceinline__ void run_mma(float acc[16][4], const uint32_t* U,
                                        const uint4* Wp4, const TileCtx& c) {
    #pragma unroll
    for (int nt = 0; nt < 16; nt++)
        #pragma unroll
        for (int i = 0; i < 4; i++) acc[nt][i] = 0.f;
    #pragma unroll
    for (int ks = 0; ks < KSTEPS; ks++) {
        uint32_t a0 = U[(c.m0 + c.r    ) * NFS + ks * 8 + c.cq    ];
        uint32_t a1 = U[(c.m0 + c.r + 8) * NFS + ks * 8 + c.cq    ];
        uint32_t a2 = U[(c.m0 + c.r    ) * NFS + ks * 8 + c.cq + 4];
        uint32_t a3 = U[(c.m0 + c.r + 8) * NFS + ks * 8 + c.cq + 4];
        #pragma unroll
        for (int ntp = 0; ntp < 8; ntp++) {
            uint4 b = Wp4[(ks * 8 + ntp) * 32 + c.lane];
            MMA_TF32(acc[2*ntp  ][0], acc[2*ntp  ][1], acc[2*ntp  ][2], acc[2*ntp  ][3],
                     a0, a1, a2, a3, b.x, b.y);
            MMA_TF32(acc[2*ntp+1][0], acc[2*ntp+1][1], acc[2*ntp+1][2], acc[2*ntp+1][3],
                     a0, a1, a2, a3, b.z, b.w);
        }
    }
}

__device__ __forceinline__ void stage_C(float* Cs, const float acc[16][4],
                                        const TileCtx& c, int h) {
    if ((c.warp >> 1) == h) {
        int rl = c.m0 - h * 32 + c.r;
        #pragma unroll
        for (int nt = 0; nt < 16; nt++) {
            int jc = nt * 8 + 2 * c.cq;
            *(float2*)&Cs[(rl    ) * CSS + jc] = make_float2(acc[nt][0], acc[nt][1]);
            *(float2*)&Cs[(rl + 8) * CSS + jc] = make_float2(acc[nt][2], acc[nt][3]);
        }
    }
}

// ---------------- kernels ----------------

// h = atom_fea @ W_emb + b_emb    [NA,92]@[92,64]
__global__ void k_embed(const float* __restrict__ atom,
                        const float* __restrict__ W,
                        const float* __restrict__ b) {
    __shared__ float sW[ORIG * FF];
    __shared__ float sb[FF];
    __shared__ float sa[ORIG];
    int tid = threadIdx.x;            // 64 threads
    for (int i = tid; i < ORIG * FF; i += 64) sW[i] = W[i];
    if (tid < FF) sb[tid] = b[tid];
    __syncthreads();
    for (int r = 0; r < 64; r++) {
        int row = blockIdx.x * 64 + r;
        if (row >= NA) break;
        __syncthreads();
        for (int i = tid; i < ORIG; i += 64) sa[i] = atom[row * ORIG + i];
        __syncthreads();
        float acc = sb[tid];
        #pragma unroll 4
        for (int k = 0; k < ORIG; k++) acc = fmaf(sa[k], sW[k * FF + tid], acc);
        g_h[row * FF + tid] = acc;
    }
}

// A[n,j] = sum_k h[n,k] * Wf[k,j];  P[n,j] = sum_k h[n,k] * Wf[64+k,j]
__global__ void __launch_bounds__(128) k_AP(const float* __restrict__ Wf) {
    __shared__ float sh[4][FF];
    int j = threadIdx.x;
    int n0 = blockIdx.x * 4;
    for (int i = j; i < 4 * FF; i += 128) {
        int r = i >> 6, k = i & 63;
        sh[r][k] = g_h[(n0 + r) * FF + k];
    }
    __syncthreads();
    float a0 = 0, a1 = 0, a2 = 0, a3 = 0;
    float p0 = 0, p1 = 0, p2 = 0, p3 = 0;
    #pragma unroll
    for (int k = 0; k < FF; k++) {
        float wa = __ldg(&Wf[k * TWOF + j]);
        float wb = __ldg(&Wf[(FF + k) * TWOF + j]);
        a0 = fmaf(sh[0][k], wa, a0); p0 = fmaf(sh[0][k], wb, p0);
        a1 = fmaf(sh[1][k], wa, a1); p1 = fmaf(sh[1][k], wb, p1);
        a2 = fmaf(sh[2][k], wa, a2); p2 = fmaf(sh[2][k], wb, p2);
        a3 = fmaf(sh[3][k], wa, a3); p3 = fmaf(sh[3][k], wb, p3);
    }
    g_A[(n0 + 0) * TWOF + j] = a0;  g_P[(n0 + 0) * TWOF + j] = p0;
    g_A[(n0 + 1) * TWOF + j] = a1;  g_P[(n0 + 1) * TWOF + j] = p1;
    g_A[(n0 + 2) * TWOF + j] = a2;  g_P[(n0 + 2) * TWOF + j] = p2;
    g_A[(n0 + 3) * TWOF + j] = a3;  g_P[(n0 + 3) * TWOF + j] = p3;
}

// zero the stat accumulators only (g_summed is overwritten by k_S2)
__global__ void k_zero() {
    int i = threadIdx.x;
    if (i < 2 * TWOF) g_stat1[i] = 0.0;
    if (i < 2 * FF)   g_stat2[i] = 0.0;
}

// ---------------------------------------------------------------------
// Pass 1: k_G1 — tf32 GEMM + A(smem)/P(float4) gather + bias ->
// column stats (fp32 accum -> fp64 atomic) + fp16 spill of G.
// Epilogue threads: jq = tid&31 (col quad), g = tid>>5 (8-edge subgroup).
// ---------------------------------------------------------------------
__global__ void __launch_bounds__(128, 5) k_G1(const float* __restrict__ nbr_fea,
                                               const int*   __restrict__ idx,
                                               const float* __restrict__ Wf,
                                               const float* __restrict__ bf) {
    __shared__ uint4 Wp4[KSTEPS * 8 * 32];            // 24.0 KB
    __shared__ __align__(16) float Cs[32 * CSS];      // 16.9 KB; aliased by U
    __shared__ __align__(16) float As[NATILE * TWOF]; // 3.5 KB
    __shared__ int sidx[TILE_E];
    uint32_t* U = (uint32_t*)Cs;                      // 3136 <= 32*CSS = 4224

    TileCtx c;
    c.tid = threadIdx.x; c.lane = c.tid & 31; c.warp = c.tid >> 5;
    c.m0 = c.warp * 16; c.r = c.lane >> 2; c.cq = c.lane & 3;
    int tid = c.tid;

    pack_B(Wp4, Wf, tid);

    int jq = tid & 31;           // column quad: cols 4jq..4jq+3
    int g  = tid >> 5;           // edge subgroup (8 edges) within 32-half
    float4 bf4 = __ldg((const float4*)&bf[4 * jq]);

    float ds0 = 0, ds1 = 0, ds2 = 0, ds3 = 0;
    float dq0 = 0, dq1 = 0, dq2 = 0, dq3 = 0;

    for (int t = blockIdx.x; t < NTILES; t += gridDim.x) {
        int e0 = t * TILE_E;
        int n_first = e0 / MM;
        __syncthreads();
        stage_NF(U, nbr_fea, e0, tid);
        stage_A(As, n_first, tid);
        if (tid < TILE_E) sidx[tid] = idx[e0 + tid];
        __syncthreads();

        float acc[16][4];
        run_mma(acc, U, Wp4, c);
        __syncthreads();

        #pragma unroll
        for (int h = 0; h < 2; h++) {
            stage_C(Cs, acc, c, h);
            __syncthreads();
            int eg = e0 + h * 32 + g * 8;
            int n  = eg / MM;
            int rem = eg - n * MM;
            int nl  = n - n_first;
            float ts0 = 0, ts1 = 0, ts2 = 0, ts3 = 0;
            float tq0 = 0, tq1 = 0, tq2 = 0, tq3 = 0;
            #pragma unroll
            for (int i = 0; i < 8; i++) {
                int le = g * 8 + i;
                int nb = sidx[h * 32 + le];
                float4 P = __ldg((const float4*)&g_P[(size_t)nb * TWOF + 4 * jq]);
                float4 A = *(const float4*)&As[nl * TWOF + 4 * jq];
                float4 C = *(const float4*)&Cs[le * CSS + 4 * jq];
                float v0 = C.x + A.x + P.x + bf4.x;
                float v1 = C.y + A.y + P.y + bf4.y;
                float v2 = C.z + A.z + P.z + bf4.z;
                float v3 = C.w + A.w + P.w + bf4.w;
                ts0 += v0; tq0 = fmaf(v0, v0, tq0);
                ts1 += v1; tq1 = fmaf(v1, v1, tq1);
                ts2 += v2; tq2 = fmaf(v2, v2, tq2);
                ts3 += v3; tq3 = fmaf(v3, v3, tq3);
                // fp16 spill (includes bias)
                {
                    __half2 ha = __floats2half2_rn(v0, v1);
                    __half2 hb = __floats2half2_rn(v2, v3);
                    uint2 u;
                    u.x = *reinterpret_cast<unsigned*>(&ha);
                    u.y = *reinterpret_cast<unsigned*>(&hb);
                    *reinterpret_cast<uint2*>(&g_Gh[(size_t)(eg + i) * TWOF + 4 * jq]) = u;
                }
                if (++rem == MM) { rem = 0; nl++; }
            }
            ds0 += ts0; ds1 += ts1; ds2 += ts2; ds3 += ts3;
            dq0 += tq0; dq1 += tq1; dq2 += tq2; dq3 += tq3;
            __syncthreads();
        }
    }

    atomicAdd(&g_stat1[4 * jq + 0], (double)ds0);
    atomicAdd(&g_stat1[4 * jq + 1], (double)ds1);
    atomicAdd(&g_stat1[4 * jq + 2], (double)ds2);
    atomicAdd(&g_stat1[4 * jq + 3], (double)ds3);
    atomicAdd(&g_stat1[TWOF + 4 * jq + 0], (double)dq0);
    atomicAdd(&g_stat1[TWOF + 4 * jq + 1], (double)dq1);
    atomicAdd(&g_stat1[TWOF + 4 * jq + 2], (double)dq2);
    atomicAdd(&g_stat1[TWOF + 4 * jq + 3], (double)dq3);
}

// ---------------------------------------------------------------------
// Pass 2: k_S2 — stream fp16 G, bn1 + sigmoid*softplus, per-atom reduce,
// DIRECT store to g_summed (no atomics). 256 thr = 16 atoms x 16 col-quads.
// ---------------------------------------------------------------------
__global__ void __launch_bounds__(256) k_S2() {
    int tid = threadIdx.x;
    int t = tid & 15;                 // filter col quad: cols 4t..4t+3
    int a = tid >> 4;                 // atom within block (0..15)
    int n = blockIdx.x * 16 + a;      // grid = NA/16 = 6250 exact

    float4 scf = *(const float4*)&g_bn1[4 * t];
    float4 scc = *(const float4*)&g_bn1[FF + 4 * t];
    float4 shf = *(const float4*)&g_bn1[TWOF + 4 * t];
    float4 shc = *(const float4*)&g_bn1[TWOF + FF + 4 * t];

    size_t base = (size_t)n * MM * TWOF;
    float s0 = 0, s1 = 0, s2 = 0, s3 = 0;
    #pragma unroll
    for (int m = 0; m < MM; m++) {
        uint2 uf = __ldg((const uint2*)&g_Gh[base + m * TWOF + 4 * t]);
        uint2 uc = __ldg((const uint2*)&g_Gh[base + m * TWOF + FF + 4 * t]);
        float2 f01 = __half22float2(*reinterpret_cast<__half2*>(&uf.x));
        float2 f23 = __half22float2(*reinterpret_cast<__half2*>(&uf.y));
        float2 c01 = __half22float2(*reinterpret_cast<__half2*>(&uc.x));
        float2 c23 = __half22float2(*reinterpret_cast<__half2*>(&uc.y));
        float xf0 = fmaf(scf.x, f01.x, shf.x);
        float xf1 = fmaf(scf.y, f01.y, shf.y);
        float xf2 = fmaf(scf.z, f23.x, shf.z);
        float xf3 = fmaf(scf.w, f23.y, shf.w);
        float xc0 = fmaf(scc.x, c01.x, shc.x);
        float xc1 = fmaf(scc.y, c01.y, shc.y);
        float xc2 = fmaf(scc.z, c23.x, shc.z);
        float xc3 = fmaf(scc.w, c23.y, shc.w);
        s0 = fmaf(sigmoidf_(xf0), softplusf_(xc0), s0);
        s1 = fmaf(sigmoidf_(xf1), softplusf_(xc1), s1);
        s2 = fmaf(sigmoidf_(xf2), softplusf_(xc2), s2);
        s3 = fmaf(sigmoidf_(xf3), softplusf_(xc3), s3);
    }
    *(float4*)&g_summed[n * FF + 4 * t] = make_float4(s0, s1, s2, s3);
}

// stats over g_summed (per column over atoms)
__global__ void __launch_bounds__(256) k_stat2() {
    int tid = threadIdx.x;
    int j = tid & 63;
    int grp = tid >> 6;
    float s = 0.f, s2 = 0.f;
    int nBase = blockIdx.x * 256 + grp * 64;
    for (int t = 0; t < 64; t++) {
        int n = nBase + t;
        if (n >= NA) break;
        float v = g_summed[n * FF + j];
        s += v;
        s2 = fmaf(v, v, s2);
    }
    atomicAdd(&g_stat2[j], (double)s);
    atomicAdd(&g_stat2[FF + j], (double)s2);
}

// BN affine params from accumulated stats.
__global__ void k_bnparam(int which,
                          const float* __restrict__ gamma,
                          const float* __restrict__ beta) {
    int j = threadIdx.x;
    if (which == 0) {
        if (j >= TWOF) return;
        double inv = 1.0 / (double)NM;
        double mu = g_stat1[j] * inv;
        double var = g_stat1[TWOF + j] * inv - mu * mu;
        float sc = gamma[j] * rsqrtf((float)var + 1e-5f);
        g_bn1[j] = sc;
        g_bn1[TWOF + j] = beta[j] - (float)mu * sc;
    } else {
        if (j >= FF) return;
        double inv = 1.0 / (double)NA;
        double mu = g_stat2[j] * inv;
        double var = g_stat2[FF + j] * inv - mu * mu;
        float sc = gamma[j] * rsqrtf((float)var + 1e-5f);
        g_bn2[j] = sc;
        g_bn2[FF + j] = beta[j] - (float)mu * sc;
    }
}

// h = softplus(h + bn2(summed))
__global__ void k_H() {
    int i = blockIdx.x * blockDim.x + threadIdx.x;
    if (i >= NA * FF) return;
    int j = i & 63;
    float x = fmaf(g_bn2[j], g_summed[i], g_bn2[FF + j]);
    g_h[i] = softplusf_(g_h[i] + x);
}

__global__ void k_zero_pool() {
    int i = blockIdx.x * 256 + threadIdx.x;
    if (i < BB * FF) g_pool[i] = 0.f;
    if (i < BB) g_cnt[i] = 0.f;
}

__global__ void k_pool(const int* __restrict__ cid) {
    int n = blockIdx.x;
    int c = cid[n];
    atomicAdd(&g_pool[c * FF + threadIdx.x], g_h[n * FF + threadIdx.x]);
    if (threadIdx.x == 0) atomicAdd(&g_cnt[c], 1.f);
}

// crys = pool/cnt; out[b] = softplus(crys@W_fc + b_fc) @ W_out + b_out
__global__ void k_head(const float* __restrict__ Wfc,
                       const float* __restrict__ bfc,
                       const float* __restrict__ Wout,
                       const float* __restrict__ bout,
                       float* __restrict__ out) {
    int b = blockIdx.x;
    int t = threadIdx.x;
    __shared__ float sc[FF];
    __shared__ float red[HH];
    float inv = 1.f / fmaxf(g_cnt[b], 1.f);
    if (t < FF) sc[t] = g_pool[b * FF + t] * inv;
    __syncthreads();
    float acc = bfc[t];
    #pragma unroll
    for (int k = 0; k < FF; k++) acc = fmaf(sc[k], __ldg(&Wfc[k * HH + t]), acc);
    red[t] = softplusf_(acc) * __ldg(&Wout[t]);
    __syncthreads();
    for (int off = 64; off > 0; off >>= 1) {
        if (t < off) red[t] += red[t + off];
        __syncthreads();
    }
    if (t == 0) out[b] = red[0] + bout[0];
}

// ---------------- launch ----------------
extern "C" void kernel_launch(void* const* d_in, const int* in_sizes, int n_in,
                              void* d_out, int out_size) {
    const float* atom_fea = (const float*)d_in[0];
    const float* nbr_fea  = (const float*)d_in[1];
    const int*   nbr_idx  = (const int*)d_in[2];
    const int*   cid      = (const int*)d_in[3];
    int o = (n_in >= 17 && in_sizes[4] == 1) ? 1 : 0;
    const float* W_emb = (const float*)d_in[4 + o];
    const float* b_emb = (const float*)d_in[5 + o];
    const float* Wf    = (const float*)d_in[6 + o];
    const float* bf    = (const float*)d_in[7 + o];
    const float* g1    = (const float*)d_in[8 + o];
    const float* b1    = (const float*)d_in[9 + o];
    const float* g2    = (const float*)d_in[10 + o];
    const float* b2    = (const float*)d_in[11 + o];
    const float* W_fc  = (const float*)d_in[12 + o];
    const float* b_fc  = (const float*)d_in[13 + o];
    const float* W_out = (const float*)d_in[14 + o];
    const float* b_out = (const float*)d_in[15 + o];
    float* out = (float*)d_out;

    k_embed<<<(NA + 63) / 64, 64>>>(atom_fea, W_emb, b_emb);

    for (int l = 0; l < NCONV; l++) {
        const float* Wfl = Wf + l * WF_STRIDE;
        const float* bfl = bf + l * TWOF;
        const float* g1l = g1 + l * TWOF;
        const float* b1l = b1 + l * TWOF;
        const float* g2l = g2 + l * FF;
        const float* b2l = b2 + l * FF;

        k_zero<<<1, 384>>>();
        k_AP<<<NA / 4, 128>>>(Wfl);
        k_G1<<<KG_GRID, 128>>>(nbr_fea, nbr_idx, Wfl, bfl);
        k_bnparam<<<1, 128>>>(0, g1l, b1l);
        k_S2<<<NA / 16, 256>>>();
        k_stat2<<<(NA + 255) / 256, 256>>>();
        k_bnparam<<<1, 64>>>(1, g2l, b2l);
        k_H<<<(NA * FF) / 256, 256>>>();
    }

    k_zero_pool<<<(BB * FF + 255) / 256, 256>>>();
    k_pool<<<NA, FF>>>(cid);
    k_head<<<BB, HH>>>(W_fc, b_fc, W_out, b_out, out);
}